// round 2
// baseline (speedup 1.0000x reference)
#include <cuda_runtime.h>
#include <math.h>
#include <stdint.h>

#define FULLMASK 0xffffffffu

static const int B  = 8;
static const int N0 = 4096;
static const int N1 = 1024;
static const int N2 = 256;

// ---------------- scratch (device globals: no allocations allowed) ----------
__device__ float d_feat0[B*N0*8];      // (B,N0,8)  channels-last
__device__ float d_kf1 [B*N0*32];      // (B,N0,32) channels-last
__device__ float d_qc1 [B*3*N1];       // (B,3,N1)  channels-first
__device__ float d_qf1 [B*N1*32];      // (B,N1,32)
__device__ float d_qf2 [B*N1*64];      // (B,N1,64)
__device__ float d_kf3 [B*N1*64];      // (B,N1,64)
__device__ float d_qf3 [B*N2*64];      // (B,N2,64)
__device__ int   d_nidx[B*N0*16];      // knn indices (reused)
__device__ int   d_fidx[B*N1];         // fps indices (reused)
__device__ float d_h   [B*N0*32*16];   // h scratch (b,q,o,k) layout, 67MB (reused)
__device__ float d_gsum[B*4];
__device__ float d_gsq [B*4];

// ---------------- feat = Wt @ pc + bt ---------------------------------------
__global__ void feat_kernel(const float* __restrict__ pc, const float* __restrict__ Wt,
                            const float* __restrict__ bt, float* __restrict__ out) {
    int lin = blockIdx.x*blockDim.x + threadIdx.x;
    if (lin >= B*N0*8) return;
    int o = lin & 7;
    int n = (lin >> 3) & (N0-1);
    int b = lin / (N0*8);
    float v = bt[o];
    #pragma unroll
    for (int c = 0; c < 3; c++) v = fmaf(Wt[o*3+c], pc[(b*3+c)*N0 + n], v);
    out[lin] = v;
}

// ---------------- KNN (top-16 smallest d2, tie -> lower index) --------------
// d2 computed exactly as reference: (q2 + k2) - 2*dot, no FMA contraction.
__global__ void knn_kernel(const float* __restrict__ qc, const float* __restrict__ kc,
                           int* __restrict__ nidx, int Q, int Kn) {
    __shared__ float4 sk[128];
    int b = blockIdx.y;
    int q = blockIdx.x*128 + threadIdx.x;
    float x = qc[(b*3+0)*Q + q];
    float y = qc[(b*3+1)*Q + q];
    float z = qc[(b*3+2)*Q + q];
    float q2 = __fadd_rn(__fadd_rn(__fmul_rn(x,x), __fmul_rn(y,y)), __fmul_rn(z,z));
    float bd[16]; int bi[16];
    #pragma unroll
    for (int r = 0; r < 16; r++) { bd[r] = 3.4e38f; bi[r] = 0; }
    for (int t = 0; t < Kn; t += 128) {
        int j = t + threadIdx.x;
        float kx = kc[(b*3+0)*Kn + j];
        float ky = kc[(b*3+1)*Kn + j];
        float kz = kc[(b*3+2)*Kn + j];
        float k2 = __fadd_rn(__fadd_rn(__fmul_rn(kx,kx), __fmul_rn(ky,ky)), __fmul_rn(kz,kz));
        __syncthreads();
        sk[threadIdx.x] = make_float4(kx, ky, kz, k2);
        __syncthreads();
        #pragma unroll 4
        for (int kk = 0; kk < 128; kk++) {
            float4 s = sk[kk];
            float dot = __fadd_rn(__fadd_rn(__fmul_rn(x,s.x), __fmul_rn(y,s.y)), __fmul_rn(z,s.z));
            float d2  = __fsub_rn(__fadd_rn(q2, s.w), __fmul_rn(2.0f, dot));
            if (d2 < bd[15]) {
                bd[15] = d2; bi[15] = t + kk;
                #pragma unroll
                for (int r = 15; r > 0; --r) {
                    if (bd[r] < bd[r-1]) {
                        float td = bd[r]; bd[r] = bd[r-1]; bd[r-1] = td;
                        int   ti = bi[r]; bi[r] = bi[r-1]; bi[r-1] = ti;
                    }
                }
            }
        }
    }
    #pragma unroll
    for (int r = 0; r < 16; r++) nidx[(q + b*Q)*16 + r] = bi[r];
}

// ---------------- edge conv h = W @ [neigh-qe ; qe], fused GN stats ---------
// h layout: (b, q, o, k). Stats accumulated per (b, group) via atomics.
template<int CIN, int COUT>
__global__ void edge_h_kernel(const float* __restrict__ qf, const float* __restrict__ kf,
                              const int* __restrict__ nidx, const float* __restrict__ W,
                              float* __restrict__ h, float* __restrict__ gsum,
                              float* __restrict__ gsq, int Q, int Kn) {
    __shared__ float s_qe[CIN];
    __shared__ float s_nb[16][CIN+1];
    __shared__ float s_base[COUT];
    __shared__ int   s_idx[16];
    __shared__ float s_gs[4], s_gq[4];
    const int b = blockIdx.y, q = blockIdx.x, tid = threadIdx.x;

    if (tid < 16)  s_idx[tid] = nidx[(b*Q+q)*16 + tid];
    if (tid < CIN) s_qe[tid]  = qf[(b*Q+q)*CIN + tid];
    if (tid < 4)   { s_gs[tid] = 0.f; s_gq[tid] = 0.f; }
    __syncthreads();

    for (int e = tid; e < 16*CIN; e += 256) {
        int k = e / CIN, c = e % CIN;
        s_nb[k][c] = kf[((size_t)(b*Kn + s_idx[k]))*CIN + c];
    }
    if (tid < COUT) {
        float a = 0.f;
        #pragma unroll
        for (int c = 0; c < CIN; c++)
            a = fmaf(W[tid*2*CIN + CIN + c] - W[tid*2*CIN + c], s_qe[c], a);
        s_base[tid] = a;
    }
    __syncthreads();

    float ls0=0,ls1=0,ls2=0,ls3=0,lq0=0,lq1=0,lq2=0,lq3=0;
    const int GQ = COUT/4;
    #pragma unroll
    for (int i = tid; i < COUT*16; i += 256) {
        int o = i >> 4, k = i & 15;
        float acc = s_base[o];
        #pragma unroll
        for (int c = 0; c < CIN; c++) acc = fmaf(W[o*2*CIN + c], s_nb[k][c], acc);
        h[((size_t)(b*Q+q)*COUT + o)*16 + k] = acc;
        float a2 = acc*acc;
        int g = o / GQ;
        if      (g == 0) { ls0 += acc; lq0 += a2; }
        else if (g == 1) { ls1 += acc; lq1 += a2; }
        else if (g == 2) { ls2 += acc; lq2 += a2; }
        else             { ls3 += acc; lq3 += a2; }
    }
    #pragma unroll
    for (int off = 16; off; off >>= 1) {
        ls0 += __shfl_down_sync(FULLMASK, ls0, off);
        ls1 += __shfl_down_sync(FULLMASK, ls1, off);
        ls2 += __shfl_down_sync(FULLMASK, ls2, off);
        ls3 += __shfl_down_sync(FULLMASK, ls3, off);
        lq0 += __shfl_down_sync(FULLMASK, lq0, off);
        lq1 += __shfl_down_sync(FULLMASK, lq1, off);
        lq2 += __shfl_down_sync(FULLMASK, lq2, off);
        lq3 += __shfl_down_sync(FULLMASK, lq3, off);
    }
    if ((tid & 31) == 0) {
        atomicAdd(&s_gs[0], ls0); atomicAdd(&s_gs[1], ls1);
        atomicAdd(&s_gs[2], ls2); atomicAdd(&s_gs[3], ls3);
        atomicAdd(&s_gq[0], lq0); atomicAdd(&s_gq[1], lq1);
        atomicAdd(&s_gq[2], lq2); atomicAdd(&s_gq[3], lq3);
    }
    __syncthreads();
    if (tid < 4) {
        atomicAdd(&gsum[b*4+tid], s_gs[tid]);
        atomicAdd(&gsq [b*4+tid], s_gq[tid]);
    }
}

// ---------------- normalize + leaky + max over k ----------------------------
template<int COUT>
__global__ void finalize_kernel(const float* __restrict__ h, const float* __restrict__ gsum,
                                const float* __restrict__ gsq, const float* __restrict__ gamma,
                                const float* __restrict__ beta, float* __restrict__ out,
                                int Q, float inv_n, int cf) {
    int lin = blockIdx.x*blockDim.x + threadIdx.x;
    if (lin >= B*Q*COUT) return;
    int o = lin % COUT;
    int q = (lin / COUT) % Q;
    int b = lin / (COUT*Q);
    int g = o / (COUT/4);
    float mean = gsum[b*4+g] * inv_n;
    float var  = gsq [b*4+g] * inv_n - mean*mean;
    float inv  = 1.0f / sqrtf(var + 1e-5f);
    float sc = gamma[o] * inv;
    float sh = beta[o] - mean * sc;
    const float4* hp = (const float4*)(h + ((size_t)lin)*16);
    float m = -3.4e38f;
    #pragma unroll
    for (int v4 = 0; v4 < 4; v4++) {
        float4 hv = hp[v4];
        float vals[4] = {hv.x, hv.y, hv.z, hv.w};
        #pragma unroll
        for (int u = 0; u < 4; u++) {
            float yv = vals[u]*sc + sh;
            yv = (yv >= 0.f) ? yv : 0.2f*yv;
            m = fmaxf(m, yv);
        }
    }
    if (cf) out[(b*COUT+o)*Q + q] = m;
    else    out[((size_t)(b*Q+q))*COUT + o] = m;
}

// ---------------- farthest point sampling (sequential, 1 block/batch) -------
template<int PT>
__global__ void __launch_bounds__(1024, 1)
fps_kernel(const float* __restrict__ coords, int* __restrict__ outidx, int N, int n) {
    const int t = threadIdx.x, b = blockIdx.x;
    float px[PT], py[PT], pz[PT], dd[PT];
    #pragma unroll
    for (int r = 0; r < PT; r++) {
        int i = t + (r << 10);
        px[r] = coords[(b*3+0)*N + i];
        py[r] = coords[(b*3+1)*N + i];
        pz[r] = coords[(b*3+2)*N + i];
        dd[r] = 1e10f;
    }
    __shared__ float s_last[3];
    __shared__ float s_rv[32];
    __shared__ int   s_ri[32];
    if (t == 0) {
        outidx[b*n + 0] = 0;
        s_last[0] = coords[(b*3+0)*N];
        s_last[1] = coords[(b*3+1)*N];
        s_last[2] = coords[(b*3+2)*N];
    }
    for (int j = 1; j < n; ++j) {
        __syncthreads();
        float lx = s_last[0], ly = s_last[1], lz = s_last[2];
        float bv = -1.0f; int bi = 0;
        #pragma unroll
        for (int r = 0; r < PT; r++) {
            float dx = __fsub_rn(px[r], lx);
            float dy = __fsub_rn(py[r], ly);
            float dz = __fsub_rn(pz[r], lz);
            float d  = __fadd_rn(__fadd_rn(__fmul_rn(dx,dx), __fmul_rn(dy,dy)), __fmul_rn(dz,dz));
            dd[r] = fminf(dd[r], d);
            if (dd[r] > bv) { bv = dd[r]; bi = t + (r << 10); }
        }
        #pragma unroll
        for (int off = 16; off; off >>= 1) {
            float ov = __shfl_down_sync(FULLMASK, bv, off);
            int   oi = __shfl_down_sync(FULLMASK, bi, off);
            if (ov > bv || (ov == bv && oi < bi)) { bv = ov; bi = oi; }
        }
        if ((t & 31) == 0) { s_rv[t >> 5] = bv; s_ri[t >> 5] = bi; }
        __syncthreads();
        if (t < 32) {
            bv = s_rv[t]; bi = s_ri[t];
            #pragma unroll
            for (int off = 16; off; off >>= 1) {
                float ov = __shfl_down_sync(FULLMASK, bv, off);
                int   oi = __shfl_down_sync(FULLMASK, bi, off);
                if (ov > bv || (ov == bv && oi < bi)) { bv = ov; bi = oi; }
            }
            if (t == 0) {
                outidx[b*n + j] = bi;
                s_last[0] = coords[(b*3+0)*N + bi];
                s_last[1] = coords[(b*3+1)*N + bi];
                s_last[2] = coords[(b*3+2)*N + bi];
            }
        }
    }
}

// ---------------- gathers ----------------------------------------------------
__global__ void gather_cf(const float* __restrict__ src, const int* __restrict__ fidx,
                          float* __restrict__ dst, int N, int n) {
    int lin = blockIdx.x*blockDim.x + threadIdx.x;
    if (lin >= B*3*n) return;
    int j = lin % n; int c = (lin/n) % 3; int b = lin/(3*n);
    dst[lin] = src[(b*3+c)*N + fidx[b*n + j]];
}

__global__ void gather_cl(const float* __restrict__ src, const int* __restrict__ fidx,
                          float* __restrict__ dst, int C, int N, int n) {
    int lin = blockIdx.x*blockDim.x + threadIdx.x;
    if (lin >= B*n*C) return;
    int c = lin % C; int j = (lin/C) % n; int b = lin/(n*C);
    dst[lin] = src[((size_t)(b*N + fidx[b*n + j]))*C + c];
}

__global__ void zero_stats(float* a, float* b) {
    int t = threadIdx.x;
    if (t < 32) { a[t] = 0.f; b[t] = 0.f; }
}

// ---------------- launch ------------------------------------------------------
extern "C" void kernel_launch(void* const* d_in, const int* in_sizes, int n_in,
                              void* d_out, int out_size) {
    const float* pc = (const float*)d_in[0];
    const float* Wt = (const float*)d_in[1];
    const float* bt = (const float*)d_in[2];
    const float* W1 = (const float*)d_in[3];
    const float* g1 = (const float*)d_in[4];
    const float* b1 = (const float*)d_in[5];
    const float* W2 = (const float*)d_in[6];
    const float* g2 = (const float*)d_in[7];
    const float* b2 = (const float*)d_in[8];
    const float* W3 = (const float*)d_in[9];
    const float* g3 = (const float*)d_in[10];
    const float* b3 = (const float*)d_in[11];
    const float* W4 = (const float*)d_in[12];
    const float* g4 = (const float*)d_in[13];
    const float* b4 = (const float*)d_in[14];

    float* out    = (float*)d_out;
    float* qc_out = out;                  // (B,3,256)
    float* qf_out = out + B*3*N2;         // (B,128,256)

    float *feat0, *kf1, *qc1, *qf1, *qf2, *kf3, *qf3, *h, *gsum, *gsq;
    int *nidx, *fidx;
    cudaGetSymbolAddress((void**)&feat0, d_feat0);
    cudaGetSymbolAddress((void**)&kf1,   d_kf1);
    cudaGetSymbolAddress((void**)&qc1,   d_qc1);
    cudaGetSymbolAddress((void**)&qf1,   d_qf1);
    cudaGetSymbolAddress((void**)&qf2,   d_qf2);
    cudaGetSymbolAddress((void**)&kf3,   d_kf3);
    cudaGetSymbolAddress((void**)&qf3,   d_qf3);
    cudaGetSymbolAddress((void**)&h,     d_h);
    cudaGetSymbolAddress((void**)&gsum,  d_gsum);
    cudaGetSymbolAddress((void**)&gsq,   d_gsq);
    cudaGetSymbolAddress((void**)&nidx,  d_nidx);
    cudaGetSymbolAddress((void**)&fidx,  d_fidx);

    // feat = Wt @ pc + bt
    feat_kernel<<<(B*N0*8 + 255)/256, 256>>>(pc, Wt, bt, feat0);

    // -------- layer 1: edge_conv(coords, feat, coords, feat, W1) ------------
    knn_kernel<<<dim3(N0/128, B), 128>>>(pc, pc, nidx, N0, N0);
    zero_stats<<<1, 32>>>(gsum, gsq);
    edge_h_kernel<8,32><<<dim3(N0, B), 256>>>(feat0, feat0, nidx, W1, h, gsum, gsq, N0, N0);
    finalize_kernel<32><<<(B*N0*32 + 255)/256, 256>>>(h, gsum, gsq, g1, b1, kf1, N0,
                                                      1.0f/(8.0f*N0*16.0f), 0);
    // -------- fps 1: 4096 -> 1024 -------------------------------------------
    fps_kernel<4><<<B, 1024>>>(pc, fidx, N0, N1);
    gather_cf<<<(B*3*N1 + 255)/256, 256>>>(pc,  fidx, qc1, N0, N1);
    gather_cl<<<(B*N1*32 + 255)/256, 256>>>(kf1, fidx, qf1, 32, N0, N1);

    // -------- layer 2: edge_conv(qc1, qf1, coords, kf1, W2) -----------------
    knn_kernel<<<dim3(N1/128, B), 128>>>(qc1, pc, nidx, N1, N0);
    zero_stats<<<1, 32>>>(gsum, gsq);
    edge_h_kernel<32,64><<<dim3(N1, B), 256>>>(qf1, kf1, nidx, W2, h, gsum, gsq, N1, N0);
    finalize_kernel<64><<<(B*N1*64 + 255)/256, 256>>>(h, gsum, gsq, g2, b2, qf2, N1,
                                                      1.0f/(16.0f*N1*16.0f), 0);
    // -------- layer 3: edge_conv(qc1, qf2, qc1, qf2, W3) --------------------
    knn_kernel<<<dim3(N1/128, B), 128>>>(qc1, qc1, nidx, N1, N1);
    zero_stats<<<1, 32>>>(gsum, gsq);
    edge_h_kernel<64,64><<<dim3(N1, B), 256>>>(qf2, qf2, nidx, W3, h, gsum, gsq, N1, N1);
    finalize_kernel<64><<<(B*N1*64 + 255)/256, 256>>>(h, gsum, gsq, g3, b3, kf3, N1,
                                                      1.0f/(16.0f*N1*16.0f), 0);
    // -------- fps 2: 1024 -> 256 ---------------------------------------------
    fps_kernel<1><<<B, 1024>>>(qc1, fidx, N1, N2);
    gather_cf<<<(B*3*N2 + 255)/256, 256>>>(qc1, fidx, qc_out, N1, N2);
    gather_cl<<<(B*N2*64 + 255)/256, 256>>>(kf3, fidx, qf3, 64, N1, N2);

    // -------- layer 4: edge_conv(qc_out, qf3, qc_out, qf3, W4) --------------
    knn_kernel<<<dim3(N2/128, B), 128>>>(qc_out, qc_out, nidx, N2, N2);
    zero_stats<<<1, 32>>>(gsum, gsq);
    edge_h_kernel<64,128><<<dim3(N2, B), 256>>>(qf3, qf3, nidx, W4, h, gsum, gsq, N2, N2);
    finalize_kernel<128><<<(B*N2*128 + 255)/256, 256>>>(h, gsum, gsq, g4, b4, qf_out, N2,
                                                        1.0f/(32.0f*N2*16.0f), 1);
}

// round 3
// speedup vs baseline: 1.8274x; 1.8274x over previous
#include <cuda_runtime.h>
#include <math.h>
#include <stdint.h>

#define FULLMASK 0xffffffffu

static const int B  = 8;
static const int N0 = 4096;
static const int N1 = 1024;
static const int N2 = 256;

// ---------------- scratch (device globals) ----------------------------------
__device__ float d_feat0[B*N0*8];      // (B,N0,8)  channels-last
__device__ float d_kf1  [B*N0*32];     // (B,N0,32) channels-last
__device__ float d_qc1  [B*3*N1];      // (B,3,N1)  channels-first
__device__ float d_qf2  [B*N1*64];     // (B,N1,64)
__device__ float d_kf3  [B*N1*64];     // (B,N1,64)
__device__ float d_hmax [B*N0*32];     // per-(b,q,o) max_k h   (reused per layer)
__device__ float d_hmin [B*N0*32];     // per-(b,q,o) min_k h
__device__ int   d_nidx [B*N0*16];     // knn indices (reused)
__device__ int   d_fidx [B*N1];        // fps1 indices
__device__ int   d_fidx2[B*N2];        // fps2 indices
__device__ float d_gsum [4*B*4];       // per-layer GN sums
__device__ float d_gsq  [4*B*4];

// ---------------- FPS: 256 threads, 1 barrier/iter, packed u64 argmax -------
template<int PT>
__device__ void fps_block(const float* __restrict__ coords, int stride,
                          const int* __restrict__ cidx,
                          int N, int n, int b, int* __restrict__ outidx)
{
    const int t = threadIdx.x;
    __shared__ unsigned long long s_pack[2];
    float px[PT], py[PT], pz[PT], dd[PT];
    #pragma unroll
    for (int r = 0; r < PT; r++) {
        int i = t + (r << 8);
        int j = cidx ? cidx[b*N + i] : i;
        px[r] = coords[(b*3+0)*stride + j];
        py[r] = coords[(b*3+1)*stride + j];
        pz[r] = coords[(b*3+2)*stride + j];
        dd[r] = 1e10f;
    }
    if (t == 0) { outidx[b*n] = 0; s_pack[0] = 0ull; s_pack[1] = 0ull; }
    int lastj = cidx ? cidx[b*N] : 0;
    float lx = coords[(b*3+0)*stride + lastj];
    float ly = coords[(b*3+1)*stride + lastj];
    float lz = coords[(b*3+2)*stride + lastj];
    __syncthreads();

    for (int it = 1; it < n; ++it) {
        int cur = it & 1;
        float bv = -1.0f; int bi = 0;
        #pragma unroll
        for (int r = 0; r < PT; r++) {
            float dx = __fsub_rn(px[r], lx);
            float dy = __fsub_rn(py[r], ly);
            float dz = __fsub_rn(pz[r], lz);
            float d  = __fadd_rn(__fadd_rn(__fmul_rn(dx,dx), __fmul_rn(dy,dy)), __fmul_rn(dz,dz));
            dd[r] = fminf(dd[r], d);
            if (dd[r] > bv) { bv = dd[r]; bi = t + (r << 8); }
        }
        unsigned long long p = ((unsigned long long)it << 44)
                             | ((unsigned long long)__float_as_uint(bv) << 12)
                             | (unsigned long long)(4095 - bi);
        #pragma unroll
        for (int off = 16; off; off >>= 1) {
            unsigned long long q = __shfl_down_sync(FULLMASK, p, off);
            p = (q > p) ? q : p;
        }
        if ((t & 31) == 0) atomicMax(&s_pack[cur], p);
        __syncthreads();
        unsigned long long win = s_pack[cur];
        int sel = 4095 - (int)(win & 0xFFFull);
        if (t == 0) outidx[b*n + it] = sel;
        lastj = cidx ? cidx[b*N + sel] : sel;
        lx = coords[(b*3+0)*stride + lastj];
        ly = coords[(b*3+1)*stride + lastj];
        lz = coords[(b*3+2)*stride + lastj];
    }
}

// ---------------- KNN: 256 queries/block, optional indirection + feat -------
__device__ void knn_block(const float* __restrict__ qcoord, int qstride, const int* __restrict__ qidxmap,
                          const float* __restrict__ kcoord, int kstride, const int* __restrict__ kidxmap,
                          int Q, int Kn, int b, int qtile, int* __restrict__ nidx,
                          const int* __restrict__ omap,
                          bool dofeat, const float* __restrict__ Wt, const float* __restrict__ bt,
                          float* __restrict__ feat0)
{
    __shared__ float4 sk[256];
    const int tid = threadIdx.x;
    int q = qtile*256 + tid;
    int qr = qidxmap ? qidxmap[b*Q + q] : q;
    float x = qcoord[(b*3+0)*qstride + qr];
    float y = qcoord[(b*3+1)*qstride + qr];
    float z = qcoord[(b*3+2)*qstride + qr];
    if (dofeat) {
        float f[8];
        #pragma unroll
        for (int o = 0; o < 8; o++)
            f[o] = fmaf(Wt[o*3+2], z, fmaf(Wt[o*3+1], y, fmaf(Wt[o*3+0], x, bt[o])));
        float4* dst = (float4*)&feat0[((size_t)(b*N0 + q))*8];
        dst[0] = make_float4(f[0], f[1], f[2], f[3]);
        dst[1] = make_float4(f[4], f[5], f[6], f[7]);
    }
    float q2 = __fadd_rn(__fadd_rn(__fmul_rn(x,x), __fmul_rn(y,y)), __fmul_rn(z,z));
    float bd[16]; int bi[16];
    #pragma unroll
    for (int r = 0; r < 16; r++) { bd[r] = 3.4e38f; bi[r] = 0; }
    for (int t0 = 0; t0 < Kn; t0 += 256) {
        int j  = t0 + tid;
        int kr = kidxmap ? kidxmap[b*Kn + j] : j;
        float kx = kcoord[(b*3+0)*kstride + kr];
        float ky = kcoord[(b*3+1)*kstride + kr];
        float kz = kcoord[(b*3+2)*kstride + kr];
        float k2 = __fadd_rn(__fadd_rn(__fmul_rn(kx,kx), __fmul_rn(ky,ky)), __fmul_rn(kz,kz));
        __syncthreads();
        sk[tid] = make_float4(kx, ky, kz, k2);
        __syncthreads();
        #pragma unroll 4
        for (int kk = 0; kk < 256; kk++) {
            float4 s  = sk[kk];
            float dot = __fadd_rn(__fadd_rn(__fmul_rn(x,s.x), __fmul_rn(y,s.y)), __fmul_rn(z,s.z));
            float d2  = __fsub_rn(__fadd_rn(q2, s.w), __fmul_rn(2.0f, dot));
            if (d2 < bd[15]) {
                bd[15] = d2; bi[15] = t0 + kk;
                #pragma unroll
                for (int r = 15; r > 0; --r) {
                    if (bd[r] < bd[r-1]) {
                        float td = bd[r]; bd[r] = bd[r-1]; bd[r-1] = td;
                        int   ti = bi[r]; bi[r] = bi[r-1]; bi[r-1] = ti;
                    }
                }
            }
        }
    }
    #pragma unroll
    for (int r = 0; r < 16; r++) {
        int v = bi[r];
        nidx[((size_t)(b*Q + q))*16 + r] = omap ? omap[b*Kn + v] : v;
    }
}

// ---------------- edge conv: h in registers, emit hmax/hmin + GN stats ------
template<int CIN, int COUT, int QB>
__device__ void edge_block(int eb, const float* __restrict__ qf, int qrows, const int* __restrict__ qmap,
                           const float* __restrict__ kf, int Kn, const int* __restrict__ nidx,
                           const float* __restrict__ W,
                           float* __restrict__ hmax_o, float* __restrict__ hmin_o,
                           float* __restrict__ gsum, float* __restrict__ gsq, int Q)
{
    __shared__ float s_nb[QB][16][CIN];
    __shared__ float s_qe[QB][CIN];
    __shared__ float s_gs[4], s_gq[4];
    const int tid = threadIdx.x;
    const int b  = eb / (Q/QB);
    const int q0 = (eb % (Q/QB)) * QB;
    if (tid < 4) { s_gs[tid] = 0.f; s_gq[tid] = 0.f; }
    for (int i = tid; i < QB*(CIN/4); i += 256) {
        int ql = i / (CIN/4), c4 = i % (CIN/4);
        int row = qmap ? qmap[b*Q + q0 + ql] : (q0 + ql);
        float4 v = *(const float4*)&qf[((size_t)b*qrows + row)*CIN + c4*4];
        *(float4*)&s_qe[ql][c4*4] = v;
    }
    for (int i = tid; i < QB*16*(CIN/4); i += 256) {
        int c4 = i % (CIN/4); int r = i / (CIN/4); int k = r & 15; int ql = r >> 4;
        int nb = nidx[((size_t)(b*Q + q0 + ql))*16 + k];
        float4 v = *(const float4*)&kf[((size_t)(b*Kn) + nb)*CIN + c4*4];
        *(float4*)&s_nb[ql][k][c4*4] = v;
    }
    __syncthreads();
    const int ql = tid / COUT;
    const int o  = tid % COUT;
    float acc[16];
    #pragma unroll
    for (int k = 0; k < 16; k++) acc[k] = 0.f;
    float base = 0.f;
    const float* Wr = W + o*2*CIN;
    #pragma unroll
    for (int cc = 0; cc < CIN; cc += 4) {
        float4 w  = *(const float4*)&Wr[cc];
        float4 w2 = *(const float4*)&Wr[CIN + cc];
        float4 qe = *(const float4*)&s_qe[ql][cc];
        base = fmaf(w2.x - w.x, qe.x, base);
        base = fmaf(w2.y - w.y, qe.y, base);
        base = fmaf(w2.z - w.z, qe.z, base);
        base = fmaf(w2.w - w.w, qe.w, base);
        #pragma unroll
        for (int k = 0; k < 16; k++) {
            float4 nb4 = *(const float4*)&s_nb[ql][k][cc];
            acc[k] = fmaf(w.x, nb4.x, acc[k]);
            acc[k] = fmaf(w.y, nb4.y, acc[k]);
            acc[k] = fmaf(w.z, nb4.z, acc[k]);
            acc[k] = fmaf(w.w, nb4.w, acc[k]);
        }
    }
    float hmx = -3.4e38f, hmn = 3.4e38f, s = 0.f, sq = 0.f;
    #pragma unroll
    for (int k = 0; k < 16; k++) {
        float h = base + acc[k];
        hmx = fmaxf(hmx, h); hmn = fminf(hmn, h);
        s += h; sq = fmaf(h, h, sq);
    }
    const int width = (COUT/4 < 32) ? (COUT/4) : 32;
    #pragma unroll
    for (int off = width >> 1; off; off >>= 1) {
        s  += __shfl_down_sync(FULLMASK, s,  off, width);
        sq += __shfl_down_sync(FULLMASK, sq, off, width);
    }
    int g = o / (COUT/4);
    if ((o & (width-1)) == 0) { atomicAdd(&s_gs[g], s); atomicAdd(&s_gq[g], sq); }
    size_t ofs = ((size_t)(b*Q + q0 + ql))*COUT + o;
    hmax_o[ofs] = hmx; hmin_o[ofs] = hmn;
    __syncthreads();
    if (tid < 4) { atomicAdd(&gsum[b*4+tid], s_gs[tid]); atomicAdd(&gsq[b*4+tid], s_gq[tid]); }
}

// ---------------- finalize: y = leaky(hext*sc + sh) --------------------------
__device__ void finalize_elem(int lin, const float* __restrict__ hmax, const float* __restrict__ hmin,
                              const float* __restrict__ gsum, const float* __restrict__ gsq,
                              const float* __restrict__ gamma, const float* __restrict__ beta,
                              float* __restrict__ out, int Q, int COUT, float inv_n, bool cf)
{
    int o = lin % COUT; int t = lin / COUT; int q = t % Q; int b = t / Q;
    int g = o / (COUT/4);
    float mean = gsum[b*4+g] * inv_n;
    float var  = gsq [b*4+g] * inv_n - mean*mean;
    float inv  = 1.0f / sqrtf(var + 1e-5f);
    float sc = gamma[o] * inv;
    float sh = beta[o] - mean * sc;
    float hv = (sc >= 0.f) ? hmax[lin] : hmin[lin];
    float yv = hv*sc + sh;
    yv = (yv >= 0.f) ? yv : 0.2f*yv;
    if (cf) out[(b*COUT + o)*Q + q] = yv;
    else    out[lin] = yv;
}

// ---------------- megakernels -------------------------------------------------
__global__ void __launch_bounds__(256) kernelA(const float* __restrict__ pc,
                                               const float* __restrict__ Wt,
                                               const float* __restrict__ bt)
{
    int blk = blockIdx.x;
    if (blk < 8) {
        fps_block<16>(pc, N0, nullptr, N0, N1, blk, d_fidx);
    } else if (blk < 136) {
        int r = blk - 8;
        knn_block(pc, N0, nullptr, pc, N0, nullptr, N0, N0, r/16, r%16,
                  d_nidx, nullptr, true, Wt, bt, d_feat0);
    } else {
        int t = threadIdx.x;
        if (t < 128) { d_gsum[t] = 0.f; d_gsq[t] = 0.f; }
    }
}

__global__ void __launch_bounds__(256) kernelB(const float* __restrict__ pc,
                                               const float* __restrict__ W1)
{
    int blk = blockIdx.x;
    if (blk < 8) {
        fps_block<4>(pc, N0, d_fidx, N1, N2, blk, d_fidx2);
    } else if (blk < 8 + 4096) {
        edge_block<8,32,8>(blk - 8, d_feat0, N0, nullptr, d_feat0, N0, d_nidx, W1,
                           d_hmax, d_hmin, d_gsum + 0, d_gsq + 0, N0);
    } else {
        int lin = (blk - 4104)*256 + threadIdx.x;      // B*3*N1 = 24576
        int j = lin % N1; int c = (lin/N1) % 3; int b = lin/(3*N1);
        d_qc1[lin] = pc[(b*3+c)*N0 + d_fidx[b*N1 + j]];
    }
}

__global__ void __launch_bounds__(256) kernelC(const float* __restrict__ pc,
                                               const float* __restrict__ g1,
                                               const float* __restrict__ b1)
{
    int blk = blockIdx.x;
    if (blk < 32) {
        knn_block(d_qc1, N1, nullptr, pc, N0, nullptr, N1, N0, blk/4, blk%4,
                  d_nidx, nullptr, false, nullptr, nullptr, nullptr);
    } else {
        int lin = (blk - 32)*256 + threadIdx.x;        // B*N0*32
        finalize_elem(lin, d_hmax, d_hmin, d_gsum + 0, d_gsq + 0, g1, b1,
                      d_kf1, N0, 32, 1.0f/(8.0f*N0*16.0f), false);
    }
}

__global__ void __launch_bounds__(256) kernelD(const float* __restrict__ W2)
{
    edge_block<32,64,4>(blockIdx.x, d_kf1, N0, d_fidx, d_kf1, N0, d_nidx, W2,
                        d_hmax, d_hmin, d_gsum + 32, d_gsq + 32, N1);
}

__global__ void __launch_bounds__(256) kernelE(const float* __restrict__ g2,
                                               const float* __restrict__ b2)
{
    int blk = blockIdx.x;
    if (blk < 32) {
        knn_block(d_qc1, N1, nullptr, d_qc1, N1, nullptr, N1, N1, blk/4, blk%4,
                  d_nidx, nullptr, false, nullptr, nullptr, nullptr);
    } else {
        int lin = (blk - 32)*256 + threadIdx.x;        // B*N1*64
        finalize_elem(lin, d_hmax, d_hmin, d_gsum + 32, d_gsq + 32, g2, b2,
                      d_qf2, N1, 64, 1.0f/(16.0f*N1*16.0f), false);
    }
}

__global__ void __launch_bounds__(256) kernelF(const float* __restrict__ W3)
{
    edge_block<64,64,4>(blockIdx.x, d_qf2, N1, nullptr, d_qf2, N1, d_nidx, W3,
                        d_hmax, d_hmin, d_gsum + 64, d_gsq + 64, N1);
}

__global__ void __launch_bounds__(256) kernelG(const float* __restrict__ g3,
                                               const float* __restrict__ b3,
                                               float* __restrict__ qc_out)
{
    int blk = blockIdx.x;
    if (blk < 8) {
        knn_block(d_qc1, N1, d_fidx2, d_qc1, N1, d_fidx2, N2, N2, blk, 0,
                  d_nidx, d_fidx2, false, nullptr, nullptr, nullptr);
    } else if (blk < 8 + 2048) {
        int lin = (blk - 8)*256 + threadIdx.x;         // B*N1*64
        finalize_elem(lin, d_hmax, d_hmin, d_gsum + 64, d_gsq + 64, g3, b3,
                      d_kf3, N1, 64, 1.0f/(16.0f*N1*16.0f), false);
    } else {
        int lin = (blk - 2056)*256 + threadIdx.x;      // B*3*N2 = 6144
        int j = lin % N2; int c = (lin/N2) % 3; int b = lin/(3*N2);
        qc_out[lin] = d_qc1[(b*3+c)*N1 + d_fidx2[b*N2 + j]];
    }
}

__global__ void __launch_bounds__(256) kernelH(const float* __restrict__ W4)
{
    edge_block<64,128,2>(blockIdx.x, d_kf3, N1, d_fidx2, d_kf3, N1, d_nidx, W4,
                         d_hmax, d_hmin, d_gsum + 96, d_gsq + 96, N2);
}

__global__ void __launch_bounds__(256) kernelI(const float* __restrict__ g4,
                                               const float* __restrict__ b4,
                                               float* __restrict__ qf_out)
{
    int lin = blockIdx.x*256 + threadIdx.x;            // B*N2*128
    finalize_elem(lin, d_hmax, d_hmin, d_gsum + 96, d_gsq + 96, g4, b4,
                  qf_out, N2, 128, 1.0f/(32.0f*N2*16.0f), true);
}

// ---------------- launch ------------------------------------------------------
extern "C" void kernel_launch(void* const* d_in, const int* in_sizes, int n_in,
                              void* d_out, int out_size) {
    const float* pc = (const float*)d_in[0];
    const float* Wt = (const float*)d_in[1];
    const float* bt = (const float*)d_in[2];
    const float* W1 = (const float*)d_in[3];
    const float* g1 = (const float*)d_in[4];
    const float* b1 = (const float*)d_in[5];
    const float* W2 = (const float*)d_in[6];
    const float* g2 = (const float*)d_in[7];
    const float* b2 = (const float*)d_in[8];
    const float* W3 = (const float*)d_in[9];
    const float* g3 = (const float*)d_in[10];
    const float* b3 = (const float*)d_in[11];
    const float* W4 = (const float*)d_in[12];
    const float* g4 = (const float*)d_in[13];
    const float* b4 = (const float*)d_in[14];

    float* out    = (float*)d_out;
    float* qc_out = out;                  // (B,3,256)
    float* qf_out = out + B*3*N2;         // (B,128,256)

    kernelA<<<137, 256>>>(pc, Wt, bt);                 // fps1 || knn1+feat || zero
    kernelB<<<4200, 256>>>(pc, W1);                    // fps2 || edge1 || gather qc1
    kernelC<<<4128, 256>>>(pc, g1, b1);                // knn2 || finalize1 -> kf1
    kernelD<<<2048, 256>>>(W2);                        // edge2
    kernelE<<<2080, 256>>>(g2, b2);                    // knn3 || finalize2 -> qf2
    kernelF<<<2048, 256>>>(W3);                        // edge3
    kernelG<<<2080, 256>>>(g3, b3, qc_out);            // knn4 || finalize3 -> kf3 || qc_out
    kernelH<<<1024, 256>>>(W4);                        // edge4
    kernelI<<<1024, 256>>>(g4, b4, qf_out);            // finalize4 -> qf_out
}

// round 7
// speedup vs baseline: 2.6663x; 1.4591x over previous
#include <cuda_runtime.h>
#include <math.h>
#include <stdint.h>

#define FULLMASK 0xffffffffu

static const int B  = 8;
static const int N0 = 4096;
static const int N1 = 1024;
static const int N2 = 256;

// ---------------- scratch (device globals) ----------------------------------
__device__ float d_feat0[B*N0*8];      // (B,N0,8)  channels-last
__device__ float d_kf1  [B*N0*32];     // (B,N0,32) channels-last
__device__ float d_qc1  [B*3*N1];      // (B,3,N1)  channels-first
__device__ float d_qf2  [B*N1*64];     // (B,N1,64)
__device__ float d_kf3  [B*N1*64];     // (B,N1,64)
__device__ float d_hmax [B*N0*32];     // per-(b,q,o) max_k h (reused per layer)
__device__ float d_hmin [B*N0*32];
__device__ int   d_nidx [B*N0*16];     // knn layer1/2 indices
__device__ int   d_nidx2[B*N1*16];     // knn layer3
__device__ int   d_nidx3[B*N2*16];     // knn layer4
__device__ int   d_fidx [B*N1];        // fps1 indices
__device__ int   d_fidx2[B*N2];        // fps2 indices (local into N1 subset)
__device__ float d_gsum [4*B*4];
__device__ float d_gsq  [4*B*4];

// ---------------- warp redux helpers -----------------------------------------
__device__ __forceinline__ unsigned redux_max_u32(unsigned v) {
    unsigned r; asm("redux.sync.max.u32 %0, %1, 0xffffffff;" : "=r"(r) : "r"(v)); return r;
}
__device__ __forceinline__ unsigned redux_min_u32(unsigned v) {
    unsigned r; asm("redux.sync.min.u32 %0, %1, 0xffffffff;" : "=r"(r) : "r"(v)); return r;
}

// ---------------- FPS1: raw coords, 4096 -> 1024 ------------------------------
__device__ void fps1_block(const float* __restrict__ pc, int b, int* __restrict__ outidx)
{
    const int t = threadIdx.x;
    __shared__ unsigned long long s_win[2][8];
    const float* cx = pc + (b*3+0)*N0;
    const float* cy = pc + (b*3+1)*N0;
    const float* cz = pc + (b*3+2)*N0;
    float px[16], py[16], pz[16], dd[16];
    #pragma unroll
    for (int r = 0; r < 16; r++) {
        int i = t + (r << 8);
        px[r] = cx[i]; py[r] = cy[i]; pz[r] = cz[i]; dd[r] = 1e10f;
    }
    if (t == 0) outidx[b*N1] = 0;
    float lx = cx[0], ly = cy[0], lz = cz[0];
    for (int it = 1; it < N1; ++it) {
        float bv = -1.0f; int bi = 0;
        #pragma unroll
        for (int r = 0; r < 16; r++) {
            float dx = __fsub_rn(px[r], lx);
            float dy = __fsub_rn(py[r], ly);
            float dz = __fsub_rn(pz[r], lz);
            float d  = __fadd_rn(__fadd_rn(__fmul_rn(dx,dx), __fmul_rn(dy,dy)), __fmul_rn(dz,dz));
            dd[r] = fminf(dd[r], d);
            if (dd[r] > bv) { bv = dd[r]; bi = t + (r << 8); }
        }
        unsigned db = __float_as_uint(bv);
        unsigned m  = redux_max_u32(db);
        unsigned mi = redux_min_u32(db == m ? (unsigned)bi : 0xFFFFFFFFu);
        int cur = it & 1;
        if ((t & 31) == 0)
            s_win[cur][t >> 5] = ((unsigned long long)m << 32) | (unsigned)(~mi);
        __syncthreads();
        unsigned long long w = s_win[cur][0];
        #pragma unroll
        for (int i = 1; i < 8; i++) { unsigned long long v = s_win[cur][i]; w = (v > w) ? v : w; }
        int sel = (int)(~(unsigned)w);
        if (t == 0) outidx[b*N1 + it] = sel;
        lx = cx[sel]; ly = cy[sel]; lz = cz[sel];
    }
}

// ---------------- FPS2: staged subset coords, 1024 -> 256 ---------------------
__device__ void fps2_block(const float* __restrict__ pc, const int* __restrict__ cidx,
                           int b, int* __restrict__ outidx)
{
    const int t = threadIdx.x;
    __shared__ unsigned long long s_win[2][8];
    __shared__ float s_cx[N1], s_cy[N1], s_cz[N1];
    const float* cx = pc + (b*3+0)*N0;
    const float* cy = pc + (b*3+1)*N0;
    const float* cz = pc + (b*3+2)*N0;
    for (int i = t; i < N1; i += 256) {
        int j = cidx[b*N1 + i];
        s_cx[i] = cx[j]; s_cy[i] = cy[j]; s_cz[i] = cz[j];
    }
    if (t == 0) outidx[b*N2] = 0;
    __syncthreads();
    float px[4], py[4], pz[4], dd[4];
    #pragma unroll
    for (int r = 0; r < 4; r++) {
        int i = t + (r << 8);
        px[r] = s_cx[i]; py[r] = s_cy[i]; pz[r] = s_cz[i]; dd[r] = 1e10f;
    }
    float lx = s_cx[0], ly = s_cy[0], lz = s_cz[0];
    for (int it = 1; it < N2; ++it) {
        float bv = -1.0f; int bi = 0;
        #pragma unroll
        for (int r = 0; r < 4; r++) {
            float dx = __fsub_rn(px[r], lx);
            float dy = __fsub_rn(py[r], ly);
            float dz = __fsub_rn(pz[r], lz);
            float d  = __fadd_rn(__fadd_rn(__fmul_rn(dx,dx), __fmul_rn(dy,dy)), __fmul_rn(dz,dz));
            dd[r] = fminf(dd[r], d);
            if (dd[r] > bv) { bv = dd[r]; bi = t + (r << 8); }
        }
        unsigned db = __float_as_uint(bv);
        unsigned m  = redux_max_u32(db);
        unsigned mi = redux_min_u32(db == m ? (unsigned)bi : 0xFFFFFFFFu);
        int cur = it & 1;
        if ((t & 31) == 0)
            s_win[cur][t >> 5] = ((unsigned long long)m << 32) | (unsigned)(~mi);
        __syncthreads();
        unsigned long long w = s_win[cur][0];
        #pragma unroll
        for (int i = 1; i < 8; i++) { unsigned long long v = s_win[cur][i]; w = (v > w) ? v : w; }
        int sel = (int)(~(unsigned)w);
        if (t == 0) outidx[b*N2 + it] = sel;
        lx = s_cx[sel]; ly = s_cy[sel]; lz = s_cz[sel];
    }
}

// ---------------- KNN: 256 queries/block, optional indirection + feat --------
__device__ void knn_block(const float* __restrict__ qcoord, int qstride, const int* __restrict__ qidxmap,
                          const float* __restrict__ kcoord, int kstride, const int* __restrict__ kidxmap,
                          int Q, int Kn, int b, int qtile, int* __restrict__ nidx,
                          const int* __restrict__ omap,
                          bool dofeat, const float* __restrict__ Wt, const float* __restrict__ bt,
                          float* __restrict__ feat0)
{
    __shared__ float4 sk[256];
    const int tid = threadIdx.x;
    int q = qtile*256 + tid;
    int qr = qidxmap ? qidxmap[b*Q + q] : q;
    float x = qcoord[(b*3+0)*qstride + qr];
    float y = qcoord[(b*3+1)*qstride + qr];
    float z = qcoord[(b*3+2)*qstride + qr];
    if (dofeat) {
        float f[8];
        #pragma unroll
        for (int o = 0; o < 8; o++)
            f[o] = fmaf(Wt[o*3+2], z, fmaf(Wt[o*3+1], y, fmaf(Wt[o*3+0], x, bt[o])));
        float4* dst = (float4*)&feat0[((size_t)(b*N0 + q))*8];
        dst[0] = make_float4(f[0], f[1], f[2], f[3]);
        dst[1] = make_float4(f[4], f[5], f[6], f[7]);
    }
    float q2 = __fadd_rn(__fadd_rn(__fmul_rn(x,x), __fmul_rn(y,y)), __fmul_rn(z,z));
    float bd[16]; int bi[16];
    #pragma unroll
    for (int r = 0; r < 16; r++) { bd[r] = 3.4e38f; bi[r] = 0; }
    for (int t0 = 0; t0 < Kn; t0 += 256) {
        int j  = t0 + tid;
        int kr = kidxmap ? kidxmap[b*Kn + j] : j;
        float kx = kcoord[(b*3+0)*kstride + kr];
        float ky = kcoord[(b*3+1)*kstride + kr];
        float kz = kcoord[(b*3+2)*kstride + kr];
        float k2 = __fadd_rn(__fadd_rn(__fmul_rn(kx,kx), __fmul_rn(ky,ky)), __fmul_rn(kz,kz));
        __syncthreads();
        sk[tid] = make_float4(kx, ky, kz, k2);
        __syncthreads();
        #pragma unroll 4
        for (int kk = 0; kk < 256; kk++) {
            float4 s  = sk[kk];
            float dot = __fadd_rn(__fadd_rn(__fmul_rn(x,s.x), __fmul_rn(y,s.y)), __fmul_rn(z,s.z));
            float d2  = __fsub_rn(__fadd_rn(q2, s.w), __fmul_rn(2.0f, dot));
            if (d2 < bd[15]) {
                bd[15] = d2; bi[15] = t0 + kk;
                #pragma unroll
                for (int r = 15; r > 0; --r) {
                    if (bd[r] < bd[r-1]) {
                        float td = bd[r]; bd[r] = bd[r-1]; bd[r-1] = td;
                        int   ti = bi[r]; bi[r] = bi[r-1]; bi[r-1] = ti;
                    }
                }
            }
        }
    }
    #pragma unroll
    for (int r = 0; r < 16; r++) {
        int v = bi[r];
        nidx[((size_t)(b*Q + q))*16 + r] = omap ? omap[b*Kn + v] : v;
    }
}

// ---------------- edge conv: h in registers, emit hmax/hmin + GN stats -------
template<int CIN, int COUT, int QB>
__device__ void edge_block(int eb, const float* __restrict__ qf, int qrows, const int* __restrict__ qmap,
                           const float* __restrict__ kf, int Kn, const int* __restrict__ nidx,
                           const float* __restrict__ W,
                           float* __restrict__ hmax_o, float* __restrict__ hmin_o,
                           float* __restrict__ gsum, float* __restrict__ gsq, int Q)
{
    __shared__ float s_nb[QB][16][CIN];
    __shared__ float s_qe[QB][CIN];
    __shared__ float s_gs[4], s_gq[4];
    const int tid = threadIdx.x;
    const int b  = eb / (Q/QB);
    const int q0 = (eb % (Q/QB)) * QB;
    if (tid < 4) { s_gs[tid] = 0.f; s_gq[tid] = 0.f; }
    for (int i = tid; i < QB*(CIN/4); i += 256) {
        int ql = i / (CIN/4), c4 = i % (CIN/4);
        int row = qmap ? qmap[b*Q + q0 + ql] : (q0 + ql);
        float4 v = *(const float4*)&qf[((size_t)b*qrows + row)*CIN + c4*4];
        *(float4*)&s_qe[ql][c4*4] = v;
    }
    for (int i = tid; i < QB*16*(CIN/4); i += 256) {
        int c4 = i % (CIN/4); int r = i / (CIN/4); int k = r & 15; int ql = r >> 4;
        int nb = nidx[((size_t)(b*Q + q0 + ql))*16 + k];
        float4 v = *(const float4*)&kf[((size_t)(b*Kn) + nb)*CIN + c4*4];
        *(float4*)&s_nb[ql][k][c4*4] = v;
    }
    __syncthreads();
    const int ql = tid / COUT;
    const int o  = tid % COUT;
    float acc[16];
    #pragma unroll
    for (int k = 0; k < 16; k++) acc[k] = 0.f;
    float base = 0.f;
    const float* Wr = W + o*2*CIN;
    #pragma unroll
    for (int cc = 0; cc < CIN; cc += 4) {
        float4 w  = *(const float4*)&Wr[cc];
        float4 w2 = *(const float4*)&Wr[CIN + cc];
        float4 qe = *(const float4*)&s_qe[ql][cc];
        base = fmaf(w2.x - w.x, qe.x, base);
        base = fmaf(w2.y - w.y, qe.y, base);
        base = fmaf(w2.z - w.z, qe.z, base);
        base = fmaf(w2.w - w.w, qe.w, base);
        #pragma unroll
        for (int k = 0; k < 16; k++) {
            float4 nb4 = *(const float4*)&s_nb[ql][k][cc];
            acc[k] = fmaf(w.x, nb4.x, acc[k]);
            acc[k] = fmaf(w.y, nb4.y, acc[k]);
            acc[k] = fmaf(w.z, nb4.z, acc[k]);
            acc[k] = fmaf(w.w, nb4.w, acc[k]);
        }
    }
    float hmx = -3.4e38f, hmn = 3.4e38f, s = 0.f, sq = 0.f;
    #pragma unroll
    for (int k = 0; k < 16; k++) {
        float h = base + acc[k];
        hmx = fmaxf(hmx, h); hmn = fminf(hmn, h);
        s += h; sq = fmaf(h, h, sq);
    }
    const int width = (COUT/4 < 32) ? (COUT/4) : 32;
    #pragma unroll
    for (int off = width >> 1; off; off >>= 1) {
        s  += __shfl_down_sync(FULLMASK, s,  off, width);
        sq += __shfl_down_sync(FULLMASK, sq, off, width);
    }
    int g = o / (COUT/4);
    if ((o & (width-1)) == 0) { atomicAdd(&s_gs[g], s); atomicAdd(&s_gq[g], sq); }
    size_t ofs = ((size_t)(b*Q + q0 + ql))*COUT + o;
    hmax_o[ofs] = hmx; hmin_o[ofs] = hmn;
    __syncthreads();
    if (tid < 4) { atomicAdd(&gsum[b*4+tid], s_gs[tid]); atomicAdd(&gsq[b*4+tid], s_gq[tid]); }
}

// ---------------- finalize: y = leaky(hext*sc + sh) ---------------------------
__device__ void finalize_elem(int lin, const float* __restrict__ hmax, const float* __restrict__ hmin,
                              const float* __restrict__ gsum, const float* __restrict__ gsq,
                              const float* __restrict__ gamma, const float* __restrict__ beta,
                              float* __restrict__ out, int Q, int COUT, float inv_n, bool cf)
{
    int o = lin % COUT; int t = lin / COUT; int q = t % Q; int b = t / Q;
    int g = o / (COUT/4);
    float mean = gsum[b*4+g] * inv_n;
    float var  = gsq [b*4+g] * inv_n - mean*mean;
    float inv  = 1.0f / sqrtf(var + 1e-5f);
    float sc = gamma[o] * inv;
    float sh = beta[o] - mean * sc;
    float hv = (sc >= 0.f) ? hmax[lin] : hmin[lin];
    float yv = hv*sc + sh;
    yv = (yv >= 0.f) ? yv : 0.2f*yv;
    if (cf) out[(b*COUT + o)*Q + q] = yv;
    else    out[lin] = yv;
}

// ---------------- megakernels --------------------------------------------------
__global__ void __launch_bounds__(256) kernelA(const float* __restrict__ pc,
                                               const float* __restrict__ Wt,
                                               const float* __restrict__ bt)
{
    int blk = blockIdx.x;
    if (blk < 8) {
        fps1_block(pc, blk, d_fidx);
    } else if (blk < 136) {
        int r = blk - 8;
        knn_block(pc, N0, nullptr, pc, N0, nullptr, N0, N0, r/16, r%16,
                  d_nidx, nullptr, true, Wt, bt, d_feat0);
    } else {
        int t = threadIdx.x;
        if (t < 128) { d_gsum[t] = 0.f; d_gsq[t] = 0.f; }
    }
}

__global__ void __launch_bounds__(256) kernelB(const float* __restrict__ pc,
                                               const float* __restrict__ W1)
{
    int blk = blockIdx.x;
    if (blk < 8) {
        fps2_block(pc, d_fidx, blk, d_fidx2);
    } else if (blk < 8 + 4096) {
        edge_block<8,32,8>(blk - 8, d_feat0, N0, nullptr, d_feat0, N0, d_nidx, W1,
                           d_hmax, d_hmin, d_gsum + 0, d_gsq + 0, N0);
    } else {
        int lin = (blk - 4104)*256 + threadIdx.x;      // B*3*N1 = 24576
        int j = lin % N1; int c = (lin/N1) % 3; int b = lin/(3*N1);
        d_qc1[lin] = pc[(b*3+c)*N0 + d_fidx[b*N1 + j]];
    }
}

// knn2 || knn3 || knn4 || finalize1
__global__ void __launch_bounds__(256) kernelC(const float* __restrict__ pc,
                                               const float* __restrict__ g1,
                                               const float* __restrict__ b1)
{
    int blk = blockIdx.x;
    if (blk < 32) {
        knn_block(d_qc1, N1, nullptr, pc, N0, nullptr, N1, N0, blk/4, blk%4,
                  d_nidx, nullptr, false, nullptr, nullptr, nullptr);
    } else if (blk < 64) {
        int r = blk - 32;
        knn_block(d_qc1, N1, nullptr, d_qc1, N1, nullptr, N1, N1, r/4, r%4,
                  d_nidx2, nullptr, false, nullptr, nullptr, nullptr);
    } else if (blk < 72) {
        knn_block(d_qc1, N1, d_fidx2, d_qc1, N1, d_fidx2, N2, N2, blk - 64, 0,
                  d_nidx3, d_fidx2, false, nullptr, nullptr, nullptr);
    } else {
        int lin = (blk - 72)*256 + threadIdx.x;        // B*N0*32
        finalize_elem(lin, d_hmax, d_hmin, d_gsum + 0, d_gsq + 0, g1, b1,
                      d_kf1, N0, 32, 1.0f/(8.0f*N0*16.0f), false);
    }
}

__global__ void __launch_bounds__(256) kernelD(const float* __restrict__ W2)
{
    edge_block<32,64,4>(blockIdx.x, d_kf1, N0, d_fidx, d_kf1, N0, d_nidx, W2,
                        d_hmax, d_hmin, d_gsum + 32, d_gsq + 32, N1);
}

__global__ void __launch_bounds__(256) kernelE(const float* __restrict__ g2,
                                               const float* __restrict__ b2)
{
    int lin = blockIdx.x*256 + threadIdx.x;            // B*N1*64
    finalize_elem(lin, d_hmax, d_hmin, d_gsum + 32, d_gsq + 32, g2, b2,
                  d_qf2, N1, 64, 1.0f/(16.0f*N1*16.0f), false);
}

__global__ void __launch_bounds__(256) kernelF(const float* __restrict__ W3)
{
    edge_block<64,64,4>(blockIdx.x, d_qf2, N1, nullptr, d_qf2, N1, d_nidx2, W3,
                        d_hmax, d_hmin, d_gsum + 64, d_gsq + 64, N1);
}

__global__ void __launch_bounds__(256) kernelG(const float* __restrict__ g3,
                                               const float* __restrict__ b3,
                                               float* __restrict__ qc_out)
{
    int blk = blockIdx.x;
    if (blk < 2048) {
        int lin = blk*256 + threadIdx.x;               // B*N1*64
        finalize_elem(lin, d_hmax, d_hmin, d_gsum + 64, d_gsq + 64, g3, b3,
                      d_kf3, N1, 64, 1.0f/(16.0f*N1*16.0f), false);
    } else {
        int lin = (blk - 2048)*256 + threadIdx.x;      // B*3*N2 = 6144
        int j = lin % N2; int c = (lin/N2) % 3; int b = lin/(3*N2);
        qc_out[lin] = d_qc1[(b*3+c)*N1 + d_fidx2[b*N2 + j]];
    }
}

__global__ void __launch_bounds__(256) kernelH(const float* __restrict__ W4)
{
    edge_block<64,128,2>(blockIdx.x, d_kf3, N1, d_fidx2, d_kf3, N1, d_nidx3, W4,
                         d_hmax, d_hmin, d_gsum + 96, d_gsq + 96, N2);
}

__global__ void __launch_bounds__(256) kernelI(const float* __restrict__ g4,
                                               const float* __restrict__ b4,
                                               float* __restrict__ qf_out)
{
    int lin = blockIdx.x*256 + threadIdx.x;            // B*N2*128
    finalize_elem(lin, d_hmax, d_hmin, d_gsum + 96, d_gsq + 96, g4, b4,
                  qf_out, N2, 128, 1.0f/(32.0f*N2*16.0f), true);
}

// ---------------- launch --------------------------------------------------------
extern "C" void kernel_launch(void* const* d_in, const int* in_sizes, int n_in,
                              void* d_out, int out_size) {
    const float* pc = (const float*)d_in[0];
    const float* Wt = (const float*)d_in[1];
    const float* bt = (const float*)d_in[2];
    const float* W1 = (const float*)d_in[3];
    const float* g1 = (const float*)d_in[4];
    const float* b1 = (const float*)d_in[5];
    const float* W2 = (const float*)d_in[6];
    const float* g2 = (const float*)d_in[7];
    const float* b2 = (const float*)d_in[8];
    const float* W3 = (const float*)d_in[9];
    const float* g3 = (const float*)d_in[10];
    const float* b3 = (const float*)d_in[11];
    const float* W4 = (const float*)d_in[12];
    const float* g4 = (const float*)d_in[13];
    const float* b4 = (const float*)d_in[14];

    float* out    = (float*)d_out;
    float* qc_out = out;                  // (B,3,256)
    float* qf_out = out + B*3*N2;         // (B,128,256)

    kernelA<<<137, 256>>>(pc, Wt, bt);                 // fps1 || knn1+feat || zero
    kernelB<<<4200, 256>>>(pc, W1);                    // fps2 || edge1 || gather qc1
    kernelC<<<4168, 256>>>(pc, g1, b1);                // knn2||knn3||knn4 || finalize1
    kernelD<<<2048, 256>>>(W2);                        // edge2
    kernelE<<<2048, 256>>>(g2, b2);                    // finalize2 -> qf2
    kernelF<<<2048, 256>>>(W3);                        // edge3
    kernelG<<<2072, 256>>>(g3, b3, qc_out);            // finalize3 -> kf3 || qc_out
    kernelH<<<1024, 256>>>(W4);                        // edge4
    kernelI<<<1024, 256>>>(g4, b4, qf_out);            // finalize4 -> qf_out
}

// round 8
// speedup vs baseline: 2.6984x; 1.0120x over previous
#include <cuda_runtime.h>
#include <math.h>
#include <stdint.h>

#define FULLMASK 0xffffffffu

static const int B  = 8;
static const int N0 = 4096;
static const int N1 = 1024;
static const int N2 = 256;

// ---------------- scratch (device globals) ----------------------------------
__device__ float d_feat0[B*N0*8];      // (B,N0,8)  channels-last
__device__ float d_kf1  [B*N0*32];     // (B,N0,32) channels-last
__device__ float d_qc1  [B*3*N1];      // (B,3,N1)  channels-first
__device__ float d_qf2  [B*N1*64];     // (B,N1,64)
__device__ float d_kf3  [B*N1*64];     // (B,N1,64)
__device__ float d_hmax [B*N0*32];     // per-(b,q,o) max_k h (reused per layer)
__device__ float d_hmin [B*N0*32];
__device__ int   d_nidx [B*N0*16];     // knn layer1/2 indices
__device__ int   d_nidx2[B*N1*16];     // knn layer3
__device__ int   d_nidx3[B*N2*16];     // knn layer4
__device__ int   d_fidx [B*N1];        // fps1 indices
__device__ int   d_fidx2[B*N2];        // fps2 indices (local into N1 subset)
__device__ float d_gsum [4*B*4];
__device__ float d_gsq  [4*B*4];

// ---------------- warp redux helpers -----------------------------------------
__device__ __forceinline__ unsigned redux_max_u32(unsigned v) {
    unsigned r; asm("redux.sync.max.u32 %0, %1, 0xffffffff;" : "=r"(r) : "r"(v)); return r;
}
__device__ __forceinline__ unsigned redux_min_u32(unsigned v) {
    unsigned r; asm("redux.sync.min.u32 %0, %1, 0xffffffff;" : "=r"(r) : "r"(v)); return r;
}

// ---------------- packed f32x2 helpers ----------------------------------------
__device__ __forceinline__ unsigned long long pack2(float lo, float hi) {
    unsigned long long v;
    asm("mov.b64 %0, {%1, %2};" : "=l"(v) : "f"(lo), "f"(hi));
    return v;
}
// d = ((x-lx)^2 + (y-ly)^2) + (z-lz)^2 for two points, per-lane rn arithmetic
// (add of negated value == sub, mul/add rounding identical to scalar path).
__device__ __forceinline__ void dist2_pair(unsigned long long px2, unsigned long long py2,
                                           unsigned long long pz2,
                                           unsigned long long nlx2, unsigned long long nly2,
                                           unsigned long long nlz2,
                                           float& d0, float& d1)
{
    unsigned long long dx, dy, dz, s;
    asm("add.rn.f32x2 %0, %1, %2;" : "=l"(dx) : "l"(px2), "l"(nlx2));
    asm("add.rn.f32x2 %0, %1, %2;" : "=l"(dy) : "l"(py2), "l"(nly2));
    asm("add.rn.f32x2 %0, %1, %2;" : "=l"(dz) : "l"(pz2), "l"(nlz2));
    asm("mul.rn.f32x2 %0, %1, %1;" : "=l"(dx) : "l"(dx));
    asm("mul.rn.f32x2 %0, %1, %1;" : "=l"(dy) : "l"(dy));
    asm("mul.rn.f32x2 %0, %1, %1;" : "=l"(dz) : "l"(dz));
    asm("add.rn.f32x2 %0, %1, %2;" : "=l"(s)  : "l"(dx), "l"(dy));
    asm("add.rn.f32x2 %0, %1, %2;" : "=l"(s)  : "l"(s),  "l"(dz));
    asm("mov.b64 {%0, %1}, %2;" : "=f"(d0), "=f"(d1) : "l"(s));
}

// ---------------- FPS1: raw coords, 4096 -> 1024 ------------------------------
__device__ void fps1_block(const float* __restrict__ pc, int b, int* __restrict__ outidx)
{
    const int t = threadIdx.x;
    __shared__ unsigned long long s_win[2][8];
    const float* cx = pc + (b*3+0)*N0;
    const float* cy = pc + (b*3+1)*N0;
    const float* cz = pc + (b*3+2)*N0;
    unsigned long long px2[8], py2[8], pz2[8];
    float dd[16];
    #pragma unroll
    for (int p = 0; p < 8; p++) {
        int i0 = t + ((2*p)   << 8);
        int i1 = t + ((2*p+1) << 8);
        px2[p] = pack2(cx[i0], cx[i1]);
        py2[p] = pack2(cy[i0], cy[i1]);
        pz2[p] = pack2(cz[i0], cz[i1]);
        dd[2*p] = 1e10f; dd[2*p+1] = 1e10f;
    }
    if (t == 0) outidx[b*N1] = 0;
    float lx = cx[0], ly = cy[0], lz = cz[0];
    for (int it = 1; it < N1; ++it) {
        unsigned long long nlx2 = pack2(-lx, -lx);
        unsigned long long nly2 = pack2(-ly, -ly);
        unsigned long long nlz2 = pack2(-lz, -lz);
        float bv = -1.0f; int bi = 0;
        #pragma unroll
        for (int p = 0; p < 8; p++) {
            float d0, d1;
            dist2_pair(px2[p], py2[p], pz2[p], nlx2, nly2, nlz2, d0, d1);
            dd[2*p]   = fminf(dd[2*p],   d0);
            dd[2*p+1] = fminf(dd[2*p+1], d1);
            if (dd[2*p]   > bv) { bv = dd[2*p];   bi = t + ((2*p)   << 8); }
            if (dd[2*p+1] > bv) { bv = dd[2*p+1]; bi = t + ((2*p+1) << 8); }
        }
        unsigned db = __float_as_uint(bv);
        unsigned m  = redux_max_u32(db);
        unsigned mi = redux_min_u32(db == m ? (unsigned)bi : 0xFFFFFFFFu);
        int cur = it & 1;
        if ((t & 31) == 0)
            s_win[cur][t >> 5] = ((unsigned long long)m << 32) | (unsigned)(~mi);
        __syncthreads();
        unsigned long long w = s_win[cur][0];
        #pragma unroll
        for (int i = 1; i < 8; i++) { unsigned long long v = s_win[cur][i]; w = (v > w) ? v : w; }
        int sel = (int)(~(unsigned)w);
        if (t == 0) outidx[b*N1 + it] = sel;
        lx = cx[sel]; ly = cy[sel]; lz = cz[sel];
    }
}

// ---------------- FPS2: staged subset coords, 1024 -> 256 ---------------------
__device__ void fps2_block(const float* __restrict__ pc, const int* __restrict__ cidx,
                           int b, int* __restrict__ outidx)
{
    const int t = threadIdx.x;
    __shared__ unsigned long long s_win[2][8];
    __shared__ float s_cx[N1], s_cy[N1], s_cz[N1];
    const float* cx = pc + (b*3+0)*N0;
    const float* cy = pc + (b*3+1)*N0;
    const float* cz = pc + (b*3+2)*N0;
    for (int i = t; i < N1; i += 256) {
        int j = cidx[b*N1 + i];
        s_cx[i] = cx[j]; s_cy[i] = cy[j]; s_cz[i] = cz[j];
    }
    if (t == 0) outidx[b*N2] = 0;
    __syncthreads();
    unsigned long long px2[2], py2[2], pz2[2];
    float dd[4];
    #pragma unroll
    for (int p = 0; p < 2; p++) {
        int i0 = t + ((2*p)   << 8);
        int i1 = t + ((2*p+1) << 8);
        px2[p] = pack2(s_cx[i0], s_cx[i1]);
        py2[p] = pack2(s_cy[i0], s_cy[i1]);
        pz2[p] = pack2(s_cz[i0], s_cz[i1]);
        dd[2*p] = 1e10f; dd[2*p+1] = 1e10f;
    }
    float lx = s_cx[0], ly = s_cy[0], lz = s_cz[0];
    for (int it = 1; it < N2; ++it) {
        unsigned long long nlx2 = pack2(-lx, -lx);
        unsigned long long nly2 = pack2(-ly, -ly);
        unsigned long long nlz2 = pack2(-lz, -lz);
        float bv = -1.0f; int bi = 0;
        #pragma unroll
        for (int p = 0; p < 2; p++) {
            float d0, d1;
            dist2_pair(px2[p], py2[p], pz2[p], nlx2, nly2, nlz2, d0, d1);
            dd[2*p]   = fminf(dd[2*p],   d0);
            dd[2*p+1] = fminf(dd[2*p+1], d1);
            if (dd[2*p]   > bv) { bv = dd[2*p];   bi = t + ((2*p)   << 8); }
            if (dd[2*p+1] > bv) { bv = dd[2*p+1]; bi = t + ((2*p+1) << 8); }
        }
        unsigned db = __float_as_uint(bv);
        unsigned m  = redux_max_u32(db);
        unsigned mi = redux_min_u32(db == m ? (unsigned)bi : 0xFFFFFFFFu);
        int cur = it & 1;
        if ((t & 31) == 0)
            s_win[cur][t >> 5] = ((unsigned long long)m << 32) | (unsigned)(~mi);
        __syncthreads();
        unsigned long long w = s_win[cur][0];
        #pragma unroll
        for (int i = 1; i < 8; i++) { unsigned long long v = s_win[cur][i]; w = (v > w) ? v : w; }
        int sel = (int)(~(unsigned)w);
        if (t == 0) outidx[b*N2 + it] = sel;
        lx = s_cx[sel]; ly = s_cy[sel]; lz = s_cz[sel];
    }
}

// ---------------- KNN: 256 queries/block, optional indirection + feat --------
__device__ void knn_block(const float* __restrict__ qcoord, int qstride, const int* __restrict__ qidxmap,
                          const float* __restrict__ kcoord, int kstride, const int* __restrict__ kidxmap,
                          int Q, int Kn, int b, int qtile, int* __restrict__ nidx,
                          const int* __restrict__ omap,
                          bool dofeat, const float* __restrict__ Wt, const float* __restrict__ bt,
                          float* __restrict__ feat0)
{
    __shared__ float4 sk[256];
    const int tid = threadIdx.x;
    int q = qtile*256 + tid;
    int qr = qidxmap ? qidxmap[b*Q + q] : q;
    float x = qcoord[(b*3+0)*qstride + qr];
    float y = qcoord[(b*3+1)*qstride + qr];
    float z = qcoord[(b*3+2)*qstride + qr];
    if (dofeat) {
        float f[8];
        #pragma unroll
        for (int o = 0; o < 8; o++)
            f[o] = fmaf(Wt[o*3+2], z, fmaf(Wt[o*3+1], y, fmaf(Wt[o*3+0], x, bt[o])));
        float4* dst = (float4*)&feat0[((size_t)(b*N0 + q))*8];
        dst[0] = make_float4(f[0], f[1], f[2], f[3]);
        dst[1] = make_float4(f[4], f[5], f[6], f[7]);
    }
    float q2 = __fadd_rn(__fadd_rn(__fmul_rn(x,x), __fmul_rn(y,y)), __fmul_rn(z,z));
    float bd[16]; int bi[16];
    #pragma unroll
    for (int r = 0; r < 16; r++) { bd[r] = 3.4e38f; bi[r] = 0; }
    for (int t0 = 0; t0 < Kn; t0 += 256) {
        int j  = t0 + tid;
        int kr = kidxmap ? kidxmap[b*Kn + j] : j;
        float kx = kcoord[(b*3+0)*kstride + kr];
        float ky = kcoord[(b*3+1)*kstride + kr];
        float kz = kcoord[(b*3+2)*kstride + kr];
        float k2 = __fadd_rn(__fadd_rn(__fmul_rn(kx,kx), __fmul_rn(ky,ky)), __fmul_rn(kz,kz));
        __syncthreads();
        sk[tid] = make_float4(kx, ky, kz, k2);
        __syncthreads();
        #pragma unroll 4
        for (int kk = 0; kk < 256; kk++) {
            float4 s  = sk[kk];
            float dot = __fadd_rn(__fadd_rn(__fmul_rn(x,s.x), __fmul_rn(y,s.y)), __fmul_rn(z,s.z));
            float d2  = __fsub_rn(__fadd_rn(q2, s.w), __fmul_rn(2.0f, dot));
            if (d2 < bd[15]) {
                bd[15] = d2; bi[15] = t0 + kk;
                #pragma unroll
                for (int r = 15; r > 0; --r) {
                    if (bd[r] < bd[r-1]) {
                        float td = bd[r]; bd[r] = bd[r-1]; bd[r-1] = td;
                        int   ti = bi[r]; bi[r] = bi[r-1]; bi[r-1] = ti;
                    }
                }
            }
        }
    }
    #pragma unroll
    for (int r = 0; r < 16; r++) {
        int v = bi[r];
        nidx[((size_t)(b*Q + q))*16 + r] = omap ? omap[b*Kn + v] : v;
    }
}

// ---------------- edge conv: shared-staged W, h in regs, hmax/hmin + stats ---
// sws layout: [ s_W : COUT*(2*CIN+4) | s_nb : QB*16*CIN | s_qe : QB*CIN ] floats
template<int CIN, int COUT, int QB>
__device__ void edge_block(float* sws, int eb,
                           const float* __restrict__ qf, int qrows, const int* __restrict__ qmap,
                           const float* __restrict__ kf, int Kn, const int* __restrict__ nidx,
                           const float* __restrict__ W,
                           float* __restrict__ hmax_o, float* __restrict__ hmin_o,
                           float* __restrict__ gsum, float* __restrict__ gsq, int Q)
{
    const int STR = 2*CIN + 4;             // padded row stride (floats), odd float4 stride
    const int NF4 = 2*CIN/4;
    float* s_W  = sws;
    float* s_nb = s_W + COUT*STR;
    float* s_qe = s_nb + QB*16*CIN;
    __shared__ float s_gs[4], s_gq[4];
    const int tid = threadIdx.x;
    const int b  = eb / (Q/QB);
    const int q0 = (eb % (Q/QB)) * QB;
    if (tid < 4) { s_gs[tid] = 0.f; s_gq[tid] = 0.f; }
    // stage W (transpose-free, padded rows)
    for (int i = tid; i < COUT*NF4; i += 256) {
        int o = i / NF4, j = i % NF4;
        *(float4*)&s_W[o*STR + j*4] = ((const float4*)W)[i];
    }
    for (int i = tid; i < QB*(CIN/4); i += 256) {
        int ql = i / (CIN/4), c4 = i % (CIN/4);
        int row = qmap ? qmap[b*Q + q0 + ql] : (q0 + ql);
        float4 v = *(const float4*)&qf[((size_t)b*qrows + row)*CIN + c4*4];
        *(float4*)&s_qe[ql*CIN + c4*4] = v;
    }
    for (int i = tid; i < QB*16*(CIN/4); i += 256) {
        int c4 = i % (CIN/4); int r = i / (CIN/4); int k = r & 15; int ql = r >> 4;
        int nb = nidx[((size_t)(b*Q + q0 + ql))*16 + k];
        float4 v = *(const float4*)&kf[((size_t)(b*Kn) + nb)*CIN + c4*4];
        *(float4*)&s_nb[(ql*16 + k)*CIN + c4*4] = v;
    }
    __syncthreads();
    const int ql = tid / COUT;
    const int o  = tid % COUT;
    float acc[16];
    #pragma unroll
    for (int k = 0; k < 16; k++) acc[k] = 0.f;
    float base = 0.f;
    const float* Wr  = s_W + o*STR;
    const float* qe_ = s_qe + ql*CIN;
    const float* nb_ = s_nb + ql*16*CIN;
    #pragma unroll
    for (int cc = 0; cc < CIN; cc += 4) {
        float4 w  = *(const float4*)&Wr[cc];
        float4 w2 = *(const float4*)&Wr[CIN + cc];
        float4 qe = *(const float4*)&qe_[cc];
        base = fmaf(w2.x - w.x, qe.x, base);
        base = fmaf(w2.y - w.y, qe.y, base);
        base = fmaf(w2.z - w.z, qe.z, base);
        base = fmaf(w2.w - w.w, qe.w, base);
        #pragma unroll
        for (int k = 0; k < 16; k++) {
            float4 nb4 = *(const float4*)&nb_[k*CIN + cc];
            acc[k] = fmaf(w.x, nb4.x, acc[k]);
            acc[k] = fmaf(w.y, nb4.y, acc[k]);
            acc[k] = fmaf(w.z, nb4.z, acc[k]);
            acc[k] = fmaf(w.w, nb4.w, acc[k]);
        }
    }
    float hmx = -3.4e38f, hmn = 3.4e38f, s = 0.f, sq = 0.f;
    #pragma unroll
    for (int k = 0; k < 16; k++) {
        float h = base + acc[k];
        hmx = fmaxf(hmx, h); hmn = fminf(hmn, h);
        s += h; sq = fmaf(h, h, sq);
    }
    const int width = (COUT/4 < 32) ? (COUT/4) : 32;
    #pragma unroll
    for (int off = width >> 1; off; off >>= 1) {
        s  += __shfl_down_sync(FULLMASK, s,  off, width);
        sq += __shfl_down_sync(FULLMASK, sq, off, width);
    }
    int g = o / (COUT/4);
    if ((o & (width-1)) == 0) { atomicAdd(&s_gs[g], s); atomicAdd(&s_gq[g], sq); }
    size_t ofs = ((size_t)(b*Q + q0 + ql))*COUT + o;
    hmax_o[ofs] = hmx; hmin_o[ofs] = hmn;
    __syncthreads();
    if (tid < 4) { atomicAdd(&gsum[b*4+tid], s_gs[tid]); atomicAdd(&gsq[b*4+tid], s_gq[tid]); }
}

// ---------------- finalize: y = leaky(hext*sc + sh) ---------------------------
__device__ void finalize_elem(int lin, const float* __restrict__ hmax, const float* __restrict__ hmin,
                              const float* __restrict__ gsum, const float* __restrict__ gsq,
                              const float* __restrict__ gamma, const float* __restrict__ beta,
                              float* __restrict__ out, int Q, int COUT, float inv_n, bool cf)
{
    int o = lin % COUT; int t = lin / COUT; int q = t % Q; int b = t / Q;
    int g = o / (COUT/4);
    float mean = gsum[b*4+g] * inv_n;
    float var  = gsq [b*4+g] * inv_n - mean*mean;
    float inv  = 1.0f / sqrtf(var + 1e-5f);
    float sc = gamma[o] * inv;
    float sh = beta[o] - mean * sc;
    float hv = (sc >= 0.f) ? hmax[lin] : hmin[lin];
    float yv = hv*sc + sh;
    yv = (yv >= 0.f) ? yv : 0.2f*yv;
    if (cf) out[(b*COUT + o)*Q + q] = yv;
    else    out[lin] = yv;
}

// ---------------- megakernels --------------------------------------------------
__global__ void __launch_bounds__(256) kernelA(const float* __restrict__ pc,
                                               const float* __restrict__ Wt,
                                               const float* __restrict__ bt)
{
    int blk = blockIdx.x;
    if (blk < 8) {
        fps1_block(pc, blk, d_fidx);
    } else if (blk < 136) {
        int r = blk - 8;
        knn_block(pc, N0, nullptr, pc, N0, nullptr, N0, N0, r/16, r%16,
                  d_nidx, nullptr, true, Wt, bt, d_feat0);
    } else {
        int t = threadIdx.x;
        if (t < 128) { d_gsum[t] = 0.f; d_gsq[t] = 0.f; }
    }
}

__global__ void __launch_bounds__(256) kernelB(const float* __restrict__ pc,
                                               const float* __restrict__ W1)
{
    __shared__ float ews[32*20 + 8*16*8 + 8*8];   // edge1 workspace (1728 floats)
    int blk = blockIdx.x;
    if (blk < 8) {
        fps2_block(pc, d_fidx, blk, d_fidx2);
    } else if (blk < 8 + 4096) {
        edge_block<8,32,8>(ews, blk - 8, d_feat0, N0, nullptr, d_feat0, N0, d_nidx, W1,
                           d_hmax, d_hmin, d_gsum + 0, d_gsq + 0, N0);
    } else {
        int lin = (blk - 4104)*256 + threadIdx.x;      // B*3*N1 = 24576
        int j = lin % N1; int c = (lin/N1) % 3; int b = lin/(3*N1);
        d_qc1[lin] = pc[(b*3+c)*N0 + d_fidx[b*N1 + j]];
    }
}

// knn2 || knn3 || knn4 || finalize1
__global__ void __launch_bounds__(256) kernelC(const float* __restrict__ pc,
                                               const float* __restrict__ g1,
                                               const float* __restrict__ b1)
{
    int blk = blockIdx.x;
    if (blk < 32) {
        knn_block(d_qc1, N1, nullptr, pc, N0, nullptr, N1, N0, blk/4, blk%4,
                  d_nidx, nullptr, false, nullptr, nullptr, nullptr);
    } else if (blk < 64) {
        int r = blk - 32;
        knn_block(d_qc1, N1, nullptr, d_qc1, N1, nullptr, N1, N1, r/4, r%4,
                  d_nidx2, nullptr, false, nullptr, nullptr, nullptr);
    } else if (blk < 72) {
        knn_block(d_qc1, N1, d_fidx2, d_qc1, N1, d_fidx2, N2, N2, blk - 64, 0,
                  d_nidx3, d_fidx2, false, nullptr, nullptr, nullptr);
    } else {
        int lin = (blk - 72)*256 + threadIdx.x;        // B*N0*32
        finalize_elem(lin, d_hmax, d_hmin, d_gsum + 0, d_gsq + 0, g1, b1,
                      d_kf1, N0, 32, 1.0f/(8.0f*N0*16.0f), false);
    }
}

__global__ void __launch_bounds__(256) kernelD(const float* __restrict__ W2)
{
    extern __shared__ float dsm[];
    edge_block<32,64,4>(dsm, blockIdx.x, d_kf1, N0, d_fidx, d_kf1, N0, d_nidx, W2,
                        d_hmax, d_hmin, d_gsum + 32, d_gsq + 32, N1);
}

__global__ void __launch_bounds__(256) kernelE(const float* __restrict__ g2,
                                               const float* __restrict__ b2)
{
    int lin = blockIdx.x*256 + threadIdx.x;            // B*N1*64
    finalize_elem(lin, d_hmax, d_hmin, d_gsum + 32, d_gsq + 32, g2, b2,
                  d_qf2, N1, 64, 1.0f/(16.0f*N1*16.0f), false);
}

__global__ void __launch_bounds__(256) kernelF(const float* __restrict__ W3)
{
    extern __shared__ float dsm[];
    edge_block<64,64,4>(dsm, blockIdx.x, d_qf2, N1, nullptr, d_qf2, N1, d_nidx2, W3,
                        d_hmax, d_hmin, d_gsum + 64, d_gsq + 64, N1);
}

__global__ void __launch_bounds__(256) kernelG(const float* __restrict__ g3,
                                               const float* __restrict__ b3,
                                               float* __restrict__ qc_out)
{
    int blk = blockIdx.x;
    if (blk < 2048) {
        int lin = blk*256 + threadIdx.x;               // B*N1*64
        finalize_elem(lin, d_hmax, d_hmin, d_gsum + 64, d_gsq + 64, g3, b3,
                      d_kf3, N1, 64, 1.0f/(16.0f*N1*16.0f), false);
    } else {
        int lin = (blk - 2048)*256 + threadIdx.x;      // B*3*N2 = 6144
        int j = lin % N2; int c = (lin/N2) % 3; int b = lin/(3*N2);
        qc_out[lin] = d_qc1[(b*3+c)*N1 + d_fidx2[b*N2 + j]];
    }
}

__global__ void __launch_bounds__(256) kernelH(const float* __restrict__ W4)
{
    extern __shared__ float dsm[];
    edge_block<64,128,2>(dsm, blockIdx.x, d_kf3, N1, d_fidx2, d_kf3, N1, d_nidx3, W4,
                         d_hmax, d_hmin, d_gsum + 96, d_gsq + 96, N2);
}

__global__ void __launch_bounds__(256) kernelI(const float* __restrict__ g4,
                                               const float* __restrict__ b4,
                                               float* __restrict__ qf_out)
{
    int lin = blockIdx.x*256 + threadIdx.x;            // B*N2*128
    finalize_elem(lin, d_hmax, d_hmin, d_gsum + 96, d_gsq + 96, g4, b4,
                  qf_out, N2, 128, 1.0f/(32.0f*N2*16.0f), true);
}

// ---------------- launch --------------------------------------------------------
extern "C" void kernel_launch(void* const* d_in, const int* in_sizes, int n_in,
                              void* d_out, int out_size) {
    const float* pc = (const float*)d_in[0];
    const float* Wt = (const float*)d_in[1];
    const float* bt = (const float*)d_in[2];
    const float* W1 = (const float*)d_in[3];
    const float* g1 = (const float*)d_in[4];
    const float* b1 = (const float*)d_in[5];
    const float* W2 = (const float*)d_in[6];
    const float* g2 = (const float*)d_in[7];
    const float* b2 = (const float*)d_in[8];
    const float* W3 = (const float*)d_in[9];
    const float* g3 = (const float*)d_in[10];
    const float* b3 = (const float*)d_in[11];
    const float* W4 = (const float*)d_in[12];
    const float* g4 = (const float*)d_in[13];
    const float* b4 = (const float*)d_in[14];

    float* out    = (float*)d_out;
    float* qc_out = out;                  // (B,3,256)
    float* qf_out = out + B*3*N2;         // (B,128,256)

    // dynamic smem sizes: s_W COUT*(2CIN+4) + s_nb QB*16*CIN + s_qe QB*CIN (floats)
    const int smemD = (64*68  + 4*16*32 + 4*32) * 4;   // 26112 B
    const int smemF = (64*132 + 4*16*64 + 4*64) * 4;   // 51200 B
    const int smemH = (128*132 + 2*16*64 + 2*64) * 4;  // 76288 B
    cudaFuncSetAttribute(kernelF, cudaFuncAttributeMaxDynamicSharedMemorySize, smemF);
    cudaFuncSetAttribute(kernelH, cudaFuncAttributeMaxDynamicSharedMemorySize, smemH);

    kernelA<<<137, 256>>>(pc, Wt, bt);                 // fps1 || knn1+feat || zero
    kernelB<<<4200, 256>>>(pc, W1);                    // fps2 || edge1 || gather qc1
    kernelC<<<4168, 256>>>(pc, g1, b1);                // knn2||knn3||knn4 || finalize1
    kernelD<<<2048, 256, smemD>>>(W2);                 // edge2
    kernelE<<<2048, 256>>>(g2, b2);                    // finalize2 -> qf2
    kernelF<<<2048, 256, smemF>>>(W3);                 // edge3
    kernelG<<<2072, 256>>>(g3, b3, qc_out);            // finalize3 -> kf3 || qc_out
    kernelH<<<1024, 256, smemH>>>(W4);                 // edge4
    kernelI<<<1024, 256>>>(g4, b4, qf_out);            // finalize4 -> qf_out
}

// round 11
// speedup vs baseline: 3.1853x; 1.1805x over previous
#include <cuda_runtime.h>
#include <math.h>
#include <stdint.h>

#define FULLMASK 0xffffffffu

static const int B  = 8;
static const int N0 = 4096;
static const int N1 = 1024;
static const int N2 = 256;

// ---------------- scratch (device globals) ----------------------------------
__device__ float d_feat0[B*N0*8];      // (B,N0,8)  channels-last
__device__ float d_kf1  [B*N0*32];     // (B,N0,32) channels-last
__device__ float d_qc1  [B*3*N1];      // (B,3,N1)  channels-first
__device__ float d_qf2  [B*N1*64];     // (B,N1,64)
__device__ float d_kf3  [B*N1*64];     // (B,N1,64)
__device__ float d_hmax [B*N0*32];     // per-(b,q,o) max_k h (reused per layer)
__device__ float d_hmin [B*N0*32];
__device__ int   d_nidx [B*N0*16];     // knn layer1/2 indices
__device__ int   d_nidx2[B*N1*16];     // knn layer3
__device__ int   d_nidx3[B*N2*16];     // knn layer4
__device__ int   d_fidx [B*N1];        // fps1 indices
__device__ int   d_fidx2[B*N2];        // fps2 indices (local into N1 subset)
__device__ float d_gsum [4*B*4];
__device__ float d_gsq  [4*B*4];

// ---------------- warp redux helpers -----------------------------------------
__device__ __forceinline__ unsigned redux_max_u32(unsigned v) {
    unsigned r; asm("redux.sync.max.u32 %0, %1, 0xffffffff;" : "=r"(r) : "r"(v)); return r;
}
__device__ __forceinline__ unsigned redux_min_u32(unsigned v) {
    unsigned r; asm("redux.sync.min.u32 %0, %1, 0xffffffff;" : "=r"(r) : "r"(v)); return r;
}

// ---------------- packed f32x2 helpers ----------------------------------------
__device__ __forceinline__ unsigned long long pack2(float lo, float hi) {
    unsigned long long v;
    asm("mov.b64 %0, {%1, %2};" : "=l"(v) : "f"(lo), "f"(hi));
    return v;
}
// d = ((x-lx)^2 + (y-ly)^2) + (z-lz)^2 for two points, per-lane rn arithmetic
// (add of negated value == sub, mul/add rounding identical to scalar path).
__device__ __forceinline__ void dist2_pair(
    unsigned long long px2, unsigned long long py2, unsigned long long pz2,
    unsigned long long nlx2, unsigned long long nly2, unsigned long long nlz2,
    float& d0, float& d1)
{
    unsigned long long dx, dy, dz, s;
    asm("add.rn.f32x2 %0, %1, %2;" : "=l"(dx) : "l"(px2), "l"(nlx2));
    asm("add.rn.f32x2 %0, %1, %2;" : "=l"(dy) : "l"(py2), "l"(nly2));
    asm("add.rn.f32x2 %0, %1, %2;" : "=l"(dz) : "l"(pz2), "l"(nlz2));
    asm("mul.rn.f32x2 %0, %1, %1;" : "=l"(dx) : "l"(dx));
    asm("mul.rn.f32x2 %0, %1, %1;" : "=l"(dy) : "l"(dy));
    asm("mul.rn.f32x2 %0, %1, %1;" : "=l"(dz) : "l"(dz));
    asm("add.rn.f32x2 %0, %1, %2;" : "=l"(s)  : "l"(dx), "l"(dy));
    asm("add.rn.f32x2 %0, %1, %2;" : "=l"(s)  : "l"(s),  "l"(dz));
    asm("mov.b64 {%0, %1}, %2;" : "=f"(d0), "=f"(d1) : "l"(s));
}

// thread-local argmax over dd[NPT]: max via FMNMX tree (depth log2), then min
// encoded index among exact-equal values (matches scan-order tie-break).
template<int NPT>
__device__ __forceinline__ void fps_argmax(const float* dd, int t, float& bv, int& bi)
{
    float m[NPT];
    #pragma unroll
    for (int p = 0; p < NPT; p++) m[p] = dd[p];
    #pragma unroll
    for (int s = NPT/2; s > 0; s >>= 1)
        #pragma unroll
        for (int p = 0; p < s; p++) m[p] = fmaxf(m[p], m[p+s]);
    bv = m[0];
    int enc[NPT];
    #pragma unroll
    for (int p = 0; p < NPT; p++)
        enc[p] = (dd[p] == bv) ? (t + (p << 8)) : 0x7FFFFFFF;
    #pragma unroll
    for (int s = NPT/2; s > 0; s >>= 1)
        #pragma unroll
        for (int p = 0; p < s; p++) enc[p] = min(enc[p], enc[p+s]);
    bi = enc[0];
}

// post-barrier 8-slot winner: pairwise u64 tree (depth 3)
__device__ __forceinline__ int fps_block_winner(const unsigned long long* slot)
{
    unsigned long long v0 = slot[0], v1 = slot[1], v2 = slot[2], v3 = slot[3];
    unsigned long long v4 = slot[4], v5 = slot[5], v6 = slot[6], v7 = slot[7];
    unsigned long long a = (v0 > v1) ? v0 : v1;
    unsigned long long b = (v2 > v3) ? v2 : v3;
    unsigned long long c = (v4 > v5) ? v4 : v5;
    unsigned long long d = (v6 > v7) ? v6 : v7;
    a = (a > b) ? a : b;
    c = (c > d) ? c : d;
    a = (a > c) ? a : c;
    return (int)(~(unsigned)a);
}

// ---------------- FPS1: raw coords, 4096 -> 1024 ------------------------------
__device__ void fps1_block(const float* __restrict__ pc, int b, int* __restrict__ outidx)
{
    const int t = threadIdx.x;
    __shared__ unsigned long long s_win[2][8];
    const float* cx = pc + (b*3+0)*N0;
    const float* cy = pc + (b*3+1)*N0;
    const float* cz = pc + (b*3+2)*N0;
    unsigned long long px2[8], py2[8], pz2[8];
    float dd[16];
    #pragma unroll
    for (int p = 0; p < 8; p++) {
        int i0 = t + ((2*p)   << 8);
        int i1 = t + ((2*p+1) << 8);
        px2[p] = pack2(cx[i0], cx[i1]);
        py2[p] = pack2(cy[i0], cy[i1]);
        pz2[p] = pack2(cz[i0], cz[i1]);
        dd[2*p] = 1e10f; dd[2*p+1] = 1e10f;
    }
    if (t == 0) outidx[b*N1] = 0;
    float lx = cx[0], ly = cy[0], lz = cz[0];
    for (int it = 1; it < N1; ++it) {
        unsigned long long nlx2 = pack2(-lx, -lx);
        unsigned long long nly2 = pack2(-ly, -ly);
        unsigned long long nlz2 = pack2(-lz, -lz);
        #pragma unroll
        for (int p = 0; p < 8; p++) {
            float d0, d1;
            dist2_pair(px2[p], py2[p], pz2[p], nlx2, nly2, nlz2, d0, d1);
            dd[2*p]   = fminf(dd[2*p],   d0);
            dd[2*p+1] = fminf(dd[2*p+1], d1);
        }
        float bv; int bi;
        fps_argmax<16>(dd, t, bv, bi);
        unsigned db = __float_as_uint(bv);
        unsigned m  = redux_max_u32(db);
        unsigned mi = redux_min_u32(db == m ? (unsigned)bi : 0xFFFFFFFFu);
        int cur = it & 1;
        if ((t & 31) == 0)
            s_win[cur][t >> 5] = ((unsigned long long)m << 32) | (unsigned)(~mi);
        __syncthreads();
        int sel = fps_block_winner(s_win[cur]);
        if (t == 0) outidx[b*N1 + it] = sel;
        lx = cx[sel]; ly = cy[sel]; lz = cz[sel];
    }
}

// ---------------- FPS2: staged subset coords, 1024 -> 256 ---------------------
__device__ void fps2_block(const float* __restrict__ pc, const int* __restrict__ cidx,
                           int b, int* __restrict__ outidx)
{
    const int t = threadIdx.x;
    __shared__ unsigned long long s_win[2][8];
    __shared__ float s_cx[N1], s_cy[N1], s_cz[N1];
    const float* cx = pc + (b*3+0)*N0;
    const float* cy = pc + (b*3+1)*N0;
    const float* cz = pc + (b*3+2)*N0;
    for (int i = t; i < N1; i += 256) {
        int j = cidx[b*N1 + i];
        s_cx[i] = cx[j]; s_cy[i] = cy[j]; s_cz[i] = cz[j];
    }
    if (t == 0) outidx[b*N2] = 0;
    __syncthreads();
    unsigned long long px2[2], py2[2], pz2[2];
    float dd[4];
    #pragma unroll
    for (int p = 0; p < 2; p++) {
        int i0 = t + ((2*p)   << 8);
        int i1 = t + ((2*p+1) << 8);
        px2[p] = pack2(s_cx[i0], s_cx[i1]);
        py2[p] = pack2(s_cy[i0], s_cy[i1]);
        pz2[p] = pack2(s_cz[i0], s_cz[i1]);
        dd[2*p] = 1e10f; dd[2*p+1] = 1e10f;
    }
    float lx = s_cx[0], ly = s_cy[0], lz = s_cz[0];
    for (int it = 1; it < N2; ++it) {
        unsigned long long nlx2 = pack2(-lx, -lx);
        unsigned long long nly2 = pack2(-ly, -ly);
        unsigned long long nlz2 = pack2(-lz, -lz);
        #pragma unroll
        for (int p = 0; p < 2; p++) {
            float d0, d1;
            dist2_pair(px2[p], py2[p], pz2[p], nlx2, nly2, nlz2, d0, d1);
            dd[2*p]   = fminf(dd[2*p],   d0);
            dd[2*p+1] = fminf(dd[2*p+1], d1);
        }
        float bv; int bi;
        fps_argmax<4>(dd, t, bv, bi);
        unsigned db = __float_as_uint(bv);
        unsigned m  = redux_max_u32(db);
        unsigned mi = redux_min_u32(db == m ? (unsigned)bi : 0xFFFFFFFFu);
        int cur = it & 1;
        if ((t & 31) == 0)
            s_win[cur][t >> 5] = ((unsigned long long)m << 32) | (unsigned)(~mi);
        __syncthreads();
        int sel = fps_block_winner(s_win[cur]);
        if (t == 0) outidx[b*N2 + it] = sel;
        lx = s_cx[sel]; ly = s_cy[sel]; lz = s_cz[sel];
    }
}

// ---------------- KNN: 256 queries/block, optional indirection + feat --------
__device__ void knn_block(const float* __restrict__ qcoord, int qstride, const int* __restrict__ qidxmap,
                          const float* __restrict__ kcoord, int kstride, const int* __restrict__ kidxmap,
                          int Q, int Kn, int b, int qtile, int* __restrict__ nidx,
                          const int* __restrict__ omap,
                          bool dofeat, const float* __restrict__ Wt, const float* __restrict__ bt,
                          float* __restrict__ feat0)
{
    __shared__ float4 sk[256];
    const int tid = threadIdx.x;
    int q = qtile*256 + tid;
    int qr = qidxmap ? qidxmap[b*Q + q] : q;
    float x = qcoord[(b*3+0)*qstride + qr];
    float y = qcoord[(b*3+1)*qstride + qr];
    float z = qcoord[(b*3+2)*qstride + qr];
    if (dofeat) {
        float f[8];
        #pragma unroll
        for (int o = 0; o < 8; o++)
            f[o] = fmaf(Wt[o*3+2], z, fmaf(Wt[o*3+1], y, fmaf(Wt[o*3+0], x, bt[o])));
        float4* dst = (float4*)&feat0[((size_t)(b*N0 + q))*8];
        dst[0] = make_float4(f[0], f[1], f[2], f[3]);
        dst[1] = make_float4(f[4], f[5], f[6], f[7]);
    }
    float q2 = __fadd_rn(__fadd_rn(__fmul_rn(x,x), __fmul_rn(y,y)), __fmul_rn(z,z));
    float bd[16]; int bi[16];
    #pragma unroll
    for (int r = 0; r < 16; r++) { bd[r] = 3.4e38f; bi[r] = 0; }
    for (int t0 = 0; t0 < Kn; t0 += 256) {
        int j  = t0 + tid;
        int kr = kidxmap ? kidxmap[b*Kn + j] : j;
        float kx = kcoord[(b*3+0)*kstride + kr];
        float ky = kcoord[(b*3+1)*kstride + kr];
        float kz = kcoord[(b*3+2)*kstride + kr];
        float k2 = __fadd_rn(__fadd_rn(__fmul_rn(kx,kx), __fmul_rn(ky,ky)), __fmul_rn(kz,kz));
        __syncthreads();
        sk[tid] = make_float4(kx, ky, kz, k2);
        __syncthreads();
        #pragma unroll 4
        for (int kk = 0; kk < 256; kk++) {
            float4 s  = sk[kk];
            float dot = __fadd_rn(__fadd_rn(__fmul_rn(x,s.x), __fmul_rn(y,s.y)), __fmul_rn(z,s.z));
            float d2  = __fsub_rn(__fadd_rn(q2, s.w), __fmul_rn(2.0f, dot));
            if (d2 < bd[15]) {
                bd[15] = d2; bi[15] = t0 + kk;
                #pragma unroll
                for (int r = 15; r > 0; --r) {
                    if (bd[r] < bd[r-1]) {
                        float td = bd[r]; bd[r] = bd[r-1]; bd[r-1] = td;
                        int   ti = bi[r]; bi[r] = bi[r-1]; bi[r-1] = ti;
                    }
                }
            }
        }
    }
    #pragma unroll
    for (int r = 0; r < 16; r++) {
        int v = bi[r];
        nidx[((size_t)(b*Q + q))*16 + r] = omap ? omap[b*Kn + v] : v;
    }
}

// ---------------- KNN split: 128 queries/block, 2 threads/query (key halves) --
// For layer2: queries qc1 (cf, N1), keys pc (cf, N0=4096). Half h scans keys
// [h*2048, (h+1)*2048); merge preserves (d2, lower-index) tie order exactly.
__device__ void knn_split_block(const float* __restrict__ qc, const float* __restrict__ kc,
                                int b, int qtile, int* __restrict__ nidx)
{
    __shared__ float4 skk[512];
    __shared__ unsigned long long s_k[128][32];
    const int tid  = threadIdx.x;
    const int ql   = tid & 127;
    const int half = tid >> 7;
    int q = qtile*128 + ql;
    float x = qc[(b*3+0)*N1 + q];
    float y = qc[(b*3+1)*N1 + q];
    float z = qc[(b*3+2)*N1 + q];
    float q2 = __fadd_rn(__fadd_rn(__fmul_rn(x,x), __fmul_rn(y,y)), __fmul_rn(z,z));
    float bd[16]; int bi[16];
    #pragma unroll
    for (int r = 0; r < 16; r++) { bd[r] = 3.4e38f; bi[r] = 0; }
    const int kbase = half*2048;
    for (int t0 = 0; t0 < 2048; t0 += 256) {
        {
            int j0 = t0 + tid;            // keys for half 0
            float kx = kc[(b*3+0)*N0 + j0];
            float ky = kc[(b*3+1)*N0 + j0];
            float kz = kc[(b*3+2)*N0 + j0];
            float k2 = __fadd_rn(__fadd_rn(__fmul_rn(kx,kx), __fmul_rn(ky,ky)), __fmul_rn(kz,kz));
            int j1 = 2048 + t0 + tid;     // keys for half 1
            float kx1 = kc[(b*3+0)*N0 + j1];
            float ky1 = kc[(b*3+1)*N0 + j1];
            float kz1 = kc[(b*3+2)*N0 + j1];
            float k21 = __fadd_rn(__fadd_rn(__fmul_rn(kx1,kx1), __fmul_rn(ky1,ky1)), __fmul_rn(kz1,kz1));
            __syncthreads();
            skk[tid]       = make_float4(kx,  ky,  kz,  k2);
            skk[256 + tid] = make_float4(kx1, ky1, kz1, k21);
            __syncthreads();
        }
        const float4* sh = skk + half*256;
        #pragma unroll 4
        for (int kk = 0; kk < 256; kk++) {
            float4 s  = sh[kk];
            float dot = __fadd_rn(__fadd_rn(__fmul_rn(x,s.x), __fmul_rn(y,s.y)), __fmul_rn(z,s.z));
            float d2  = __fsub_rn(__fadd_rn(q2, s.w), __fmul_rn(2.0f, dot));
            if (d2 < bd[15]) {
                bd[15] = d2; bi[15] = kbase + t0 + kk;
                #pragma unroll
                for (int r = 15; r > 0; --r) {
                    if (bd[r] < bd[r-1]) {
                        float td = bd[r]; bd[r] = bd[r-1]; bd[r-1] = td;
                        int   ti = bi[r]; bi[r] = bi[r-1]; bi[r-1] = ti;
                    }
                }
            }
        }
    }
    // publish sorted 16-lists as packed (ordered d2 bits << 32) | idx
    #pragma unroll
    for (int r = 0; r < 16; r++) {
        unsigned dbits = __float_as_uint(bd[r]);
        dbits = (dbits & 0x80000000u) ? ~dbits : (dbits ^ 0x80000000u);   // total order
        s_k[ql][half*16 + r] = ((unsigned long long)dbits << 32) | (unsigned)bi[r];
    }
    __syncthreads();
    if (half == 0) {
        int ia = 0, ib = 0;
        #pragma unroll
        for (int r = 0; r < 16; r++) {
            unsigned long long ka = s_k[ql][min(ia,15)];
            unsigned long long kb = s_k[ql][16 + min(ib,15)];
            bool ta = (ib >= 16) || ((ia < 16) && (ka <= kb));  // tie -> half0 (lower idx)
            unsigned idx = (unsigned)(ta ? ka : kb);
            nidx[((size_t)(b*N1 + q))*16 + r] = (int)idx;
            ia += ta ? 1 : 0; ib += ta ? 0 : 1;
        }
    }
}

// ---------------- edge conv: shared-staged W, h in regs, hmax/hmin + stats ---
template<int CIN, int COUT, int QB>
__device__ void edge_block(float* sws, int eb,
                           const float* __restrict__ qf, int qrows, const int* __restrict__ qmap,
                           const float* __restrict__ kf, int Kn, const int* __restrict__ nidx,
                           const float* __restrict__ W,
                           float* __restrict__ hmax_o, float* __restrict__ hmin_o,
                           float* __restrict__ gsum, float* __restrict__ gsq, int Q)
{
    const int STR = 2*CIN + 4;
    const int NF4 = 2*CIN/4;
    float* s_W  = sws;
    float* s_nb = s_W + COUT*STR;
    float* s_qe = s_nb + QB*16*CIN;
    __shared__ float s_gs[4], s_gq[4];
    const int tid = threadIdx.x;
    const int b  = eb / (Q/QB);
    const int q0 = (eb % (Q/QB)) * QB;
    if (tid < 4) { s_gs[tid] = 0.f; s_gq[tid] = 0.f; }
    for (int i = tid; i < COUT*NF4; i += 256) {
        int o = i / NF4, j = i % NF4;
        *(float4*)&s_W[o*STR + j*4] = ((const float4*)W)[i];
    }
    for (int i = tid; i < QB*(CIN/4); i += 256) {
        int ql = i / (CIN/4), c4 = i % (CIN/4);
        int row = qmap ? qmap[b*Q + q0 + ql] : (q0 + ql);
        float4 v = *(const float4*)&qf[((size_t)b*qrows + row)*CIN + c4*4];
        *(float4*)&s_qe[ql*CIN + c4*4] = v;
    }
    for (int i = tid; i < QB*16*(CIN/4); i += 256) {
        int c4 = i % (CIN/4); int r = i / (CIN/4); int k = r & 15; int ql = r >> 4;
        int nb = nidx[((size_t)(b*Q + q0 + ql))*16 + k];
        float4 v = *(const float4*)&kf[((size_t)(b*Kn) + nb)*CIN + c4*4];
        *(float4*)&s_nb[(ql*16 + k)*CIN + c4*4] = v;
    }
    __syncthreads();
    const int ql = tid / COUT;
    const int o  = tid % COUT;
    float acc[16];
    #pragma unroll
    for (int k = 0; k < 16; k++) acc[k] = 0.f;
    float base = 0.f;
    const float* Wr  = s_W + o*STR;
    const float* qe_ = s_qe + ql*CIN;
    const float* nb_ = s_nb + ql*16*CIN;
    #pragma unroll
    for (int cc = 0; cc < CIN; cc += 4) {
        float4 w  = *(const float4*)&Wr[cc];
        float4 w2 = *(const float4*)&Wr[CIN + cc];
        float4 qe = *(const float4*)&qe_[cc];
        base = fmaf(w2.x - w.x, qe.x, base);
        base = fmaf(w2.y - w.y, qe.y, base);
        base = fmaf(w2.z - w.z, qe.z, base);
        base = fmaf(w2.w - w.w, qe.w, base);
        #pragma unroll
        for (int k = 0; k < 16; k++) {
            float4 nb4 = *(const float4*)&nb_[k*CIN + cc];
            acc[k] = fmaf(w.x, nb4.x, acc[k]);
            acc[k] = fmaf(w.y, nb4.y, acc[k]);
            acc[k] = fmaf(w.z, nb4.z, acc[k]);
            acc[k] = fmaf(w.w, nb4.w, acc[k]);
        }
    }
    float hmx = -3.4e38f, hmn = 3.4e38f, s = 0.f, sq = 0.f;
    #pragma unroll
    for (int k = 0; k < 16; k++) {
        float h = base + acc[k];
        hmx = fmaxf(hmx, h); hmn = fminf(hmn, h);
        s += h; sq = fmaf(h, h, sq);
    }
    const int width = (COUT/4 < 32) ? (COUT/4) : 32;
    #pragma unroll
    for (int off = width >> 1; off; off >>= 1) {
        s  += __shfl_down_sync(FULLMASK, s,  off, width);
        sq += __shfl_down_sync(FULLMASK, sq, off, width);
    }
    int g = o / (COUT/4);
    if ((o & (width-1)) == 0) { atomicAdd(&s_gs[g], s); atomicAdd(&s_gq[g], sq); }
    size_t ofs = ((size_t)(b*Q + q0 + ql))*COUT + o;
    hmax_o[ofs] = hmx; hmin_o[ofs] = hmn;
    __syncthreads();
    if (tid < 4) { atomicAdd(&gsum[b*4+tid], s_gs[tid]); atomicAdd(&gsq[b*4+tid], s_gq[tid]); }
}

// ---------------- finalize: y = leaky(hext*sc + sh) ---------------------------
__device__ void finalize_elem(int lin, const float* __restrict__ hmax, const float* __restrict__ hmin,
                              const float* __restrict__ gsum, const float* __restrict__ gsq,
                              const float* __restrict__ gamma, const float* __restrict__ beta,
                              float* __restrict__ out, int Q, int COUT, float inv_n, bool cf)
{
    int o = lin % COUT; int t = lin / COUT; int q = t % Q; int b = t / Q;
    int g = o / (COUT/4);
    float mean = gsum[b*4+g] * inv_n;
    float var  = gsq [b*4+g] * inv_n - mean*mean;
    float inv  = 1.0f / sqrtf(var + 1e-5f);
    float sc = gamma[o] * inv;
    float sh = beta[o] - mean * sc;
    float hv = (sc >= 0.f) ? hmax[lin] : hmin[lin];
    float yv = hv*sc + sh;
    yv = (yv >= 0.f) ? yv : 0.2f*yv;
    if (cf) out[(b*COUT + o)*Q + q] = yv;
    else    out[lin] = yv;
}

// ---------------- megakernels --------------------------------------------------
__global__ void __launch_bounds__(256) kernelA(const float* __restrict__ pc,
                                               const float* __restrict__ Wt,
                                               const float* __restrict__ bt)
{
    int blk = blockIdx.x;
    if (blk < 8) {
        fps1_block(pc, blk, d_fidx);
    } else if (blk < 136) {
        int r = blk - 8;
        knn_block(pc, N0, nullptr, pc, N0, nullptr, N0, N0, r/16, r%16,
                  d_nidx, nullptr, true, Wt, bt, d_feat0);
    } else {
        int t = threadIdx.x;
        if (t < 128) { d_gsum[t] = 0.f; d_gsq[t] = 0.f; }
    }
}

__global__ void __launch_bounds__(256) kernelB(const float* __restrict__ pc,
                                               const float* __restrict__ W1)
{
    __shared__ float ews[32*20 + 8*16*8 + 8*8];   // edge1 workspace (1728 floats)
    int blk = blockIdx.x;
    if (blk < 8) {
        fps2_block(pc, d_fidx, blk, d_fidx2);
    } else if (blk < 8 + 4096) {
        edge_block<8,32,8>(ews, blk - 8, d_feat0, N0, nullptr, d_feat0, N0, d_nidx, W1,
                           d_hmax, d_hmin, d_gsum + 0, d_gsq + 0, N0);
    } else {
        int lin = (blk - 4104)*256 + threadIdx.x;      // B*3*N1 = 24576
        int j = lin % N1; int c = (lin/N1) % 3; int b = lin/(3*N1);
        d_qc1[lin] = pc[(b*3+c)*N0 + d_fidx[b*N1 + j]];
    }
}

// knn2(split) || knn3 || knn4 || finalize1
__global__ void __launch_bounds__(256) kernelC(const float* __restrict__ pc,
                                               const float* __restrict__ g1,
                                               const float* __restrict__ b1)
{
    int blk = blockIdx.x;
    if (blk < 64) {
        knn_split_block(d_qc1, pc, blk/8, blk%8, d_nidx);
    } else if (blk < 96) {
        int r = blk - 64;
        knn_block(d_qc1, N1, nullptr, d_qc1, N1, nullptr, N1, N1, r/4, r%4,
                  d_nidx2, nullptr, false, nullptr, nullptr, nullptr);
    } else if (blk < 104) {
        knn_block(d_qc1, N1, d_fidx2, d_qc1, N1, d_fidx2, N2, N2, blk - 96, 0,
                  d_nidx3, d_fidx2, false, nullptr, nullptr, nullptr);
    } else {
        int lin = (blk - 104)*256 + threadIdx.x;       // B*N0*32
        finalize_elem(lin, d_hmax, d_hmin, d_gsum + 0, d_gsq + 0, g1, b1,
                      d_kf1, N0, 32, 1.0f/(8.0f*N0*16.0f), false);
    }
}

__global__ void __launch_bounds__(256) kernelD(const float* __restrict__ W2)
{
    extern __shared__ float dsm[];
    edge_block<32,64,4>(dsm, blockIdx.x, d_kf1, N0, d_fidx, d_kf1, N0, d_nidx, W2,
                        d_hmax, d_hmin, d_gsum + 32, d_gsq + 32, N1);
}

__global__ void __launch_bounds__(256) kernelE(const float* __restrict__ g2,
                                               const float* __restrict__ b2)
{
    int lin = blockIdx.x*256 + threadIdx.x;            // B*N1*64
    finalize_elem(lin, d_hmax, d_hmin, d_gsum + 32, d_gsq + 32, g2, b2,
                  d_qf2, N1, 64, 1.0f/(16.0f*N1*16.0f), false);
}

__global__ void __launch_bounds__(256) kernelF(const float* __restrict__ W3)
{
    extern __shared__ float dsm[];
    edge_block<64,64,4>(dsm, blockIdx.x, d_qf2, N1, nullptr, d_qf2, N1, d_nidx2, W3,
                        d_hmax, d_hmin, d_gsum + 64, d_gsq + 64, N1);
}

__global__ void __launch_bounds__(256) kernelG(const float* __restrict__ g3,
                                               const float* __restrict__ b3,
                                               float* __restrict__ qc_out)
{
    int blk = blockIdx.x;
    if (blk < 2048) {
        int lin = blk*256 + threadIdx.x;               // B*N1*64
        finalize_elem(lin, d_hmax, d_hmin, d_gsum + 64, d_gsq + 64, g3, b3,
                      d_kf3, N1, 64, 1.0f/(16.0f*N1*16.0f), false);
    } else {
        int lin = (blk - 2048)*256 + threadIdx.x;      // B*3*N2 = 6144
        int j = lin % N2; int c = (lin/N2) % 3; int b = lin/(3*N2);
        qc_out[lin] = d_qc1[(b*3+c)*N1 + d_fidx2[b*N2 + j]];
    }
}

__global__ void __launch_bounds__(256) kernelH(const float* __restrict__ W4)
{
    extern __shared__ float dsm[];
    edge_block<64,128,2>(dsm, blockIdx.x, d_kf3, N1, d_fidx2, d_kf3, N1, d_nidx3, W4,
                         d_hmax, d_hmin, d_gsum + 96, d_gsq + 96, N2);
}

__global__ void __launch_bounds__(256) kernelI(const float* __restrict__ g4,
                                               const float* __restrict__ b4,
                                               float* __restrict__ qf_out)
{
    int lin = blockIdx.x*256 + threadIdx.x;            // B*N2*128
    finalize_elem(lin, d_hmax, d_hmin, d_gsum + 96, d_gsq + 96, g4, b4,
                  qf_out, N2, 128, 1.0f/(32.0f*N2*16.0f), true);
}

// ---------------- launch --------------------------------------------------------
extern "C" void kernel_launch(void* const* d_in, const int* in_sizes, int n_in,
                              void* d_out, int out_size) {
    const float* pc = (const float*)d_in[0];
    const float* Wt = (const float*)d_in[1];
    const float* bt = (const float*)d_in[2];
    const float* W1 = (const float*)d_in[3];
    const float* g1 = (const float*)d_in[4];
    const float* b1 = (const float*)d_in[5];
    const float* W2 = (const float*)d_in[6];
    const float* g2 = (const float*)d_in[7];
    const float* b2 = (const float*)d_in[8];
    const float* W3 = (const float*)d_in[9];
    const float* g3 = (const float*)d_in[10];
    const float* b3 = (const float*)d_in[11];
    const float* W4 = (const float*)d_in[12];
    const float* g4 = (const float*)d_in[13];
    const float* b4 = (const float*)d_in[14];

    float* out    = (float*)d_out;
    float* qc_out = out;                  // (B,3,256)
    float* qf_out = out + B*3*N2;         // (B,128,256)

    const int smemD = (64*68  + 4*16*32 + 4*32) * 4;   // 26112 B
    const int smemF = (64*132 + 4*16*64 + 4*64) * 4;   // 51200 B
    const int smemH = (128*132 + 2*16*64 + 2*64) * 4;  // 76288 B
    cudaFuncSetAttribute(kernelF, cudaFuncAttributeMaxDynamicSharedMemorySize, smemF);
    cudaFuncSetAttribute(kernelH, cudaFuncAttributeMaxDynamicSharedMemorySize, smemH);

    kernelA<<<137, 256>>>(pc, Wt, bt);                 // fps1 || knn1+feat || zero
    kernelB<<<4200, 256>>>(pc, W1);                    // fps2 || edge1 || gather qc1
    kernelC<<<4200, 256>>>(pc, g1, b1);                // knn2split||knn3||knn4||finalize1
    kernelD<<<2048, 256, smemD>>>(W2);                 // edge2
    kernelE<<<2048, 256>>>(g2, b2);                    // finalize2 -> qf2
    kernelF<<<2048, 256, smemF>>>(W3);                 // edge3
    kernelG<<<2072, 256>>>(g3, b3, qc_out);            // finalize3 -> kf3 || qc_out
    kernelH<<<1024, 256, smemH>>>(W4);                 // edge4
    kernelI<<<1024, 256>>>(g4, b4, qf_out);            // finalize4 -> qf_out
}